// round 12
// baseline (speedup 1.0000x reference)
#include <cuda_runtime.h>
#include <cuda_fp16.h>
#include <math.h>
#include <string.h>
#include <stdint.h>

#define NB    8
#define LSEQ  2048
#define MTOK  (NB*LSEQ)     // 16384 tokens
#define DIN   64
#define DOUT  64
#define DM    512
#define DS    256
#define NL    4
#define NCH   16
#define CHLEN (LSEQ/NCH)    // 128

// ---------------- scratch (device globals; no allocation allowed) ----------------
__device__ float  g_x  [MTOK*DM];         // fp32 residual stream
__device__ __half g_buh[MTOK*DM];         // fp16 Bu packed [re|im]
__device__ __half g_hh [MTOK*DM];         // fp16 h  packed [re|im]
__device__ __half g_zh [MTOK*DM];         // fp16 LRU output
// weights: single-fp16 for Bu/C/GLU; hi+lo for encoder/decoder
__device__ __half g_Wb  [NL*DM*DM];
__device__ __half g_Wc  [NL*DM*DM];
__device__ __half g_Wg  [NL*2*DM*DM];
__device__ __half g_enchi[DM*DIN],    g_enclo[DM*DIN];
__device__ __half g_dechi[128*DM],    g_declo[128*DM];   // padded to 128 rows
// scan params / carries
__device__ float g_lre[NL*DS], g_lim[NL*DS], g_gam[NL*DS], g_sres[NL];
__device__ float g_cend[NB*NCH*2*DS];

// ---------------- helpers ----------------
__device__ __forceinline__ uint32_t smem_u32(const void* p) {
    uint32_t a;
    asm("{ .reg .u64 t; cvta.to.shared.u64 t, %1; cvt.u32.u64 %0, t; }" : "=r"(a) : "l"(p));
    return a;
}
__device__ __forceinline__ uint32_t sw128(uint32_t b) { return b ^ ((b >> 3) & 0x70); }

__device__ __forceinline__ void ldsm4(uint32_t* r, uint32_t addr) {
    asm volatile("ldmatrix.sync.aligned.m8n8.x4.shared.b16 {%0,%1,%2,%3}, [%4];"
                 : "=r"(r[0]), "=r"(r[1]), "=r"(r[2]), "=r"(r[3]) : "r"(addr));
}
__device__ __forceinline__ void mma_f16(float* c, const uint32_t* a, const uint32_t* b) {
    asm volatile(
        "mma.sync.aligned.m16n8k16.row.col.f32.f16.f16.f32 "
        "{%0,%1,%2,%3}, {%4,%5,%6,%7}, {%8,%9}, {%0,%1,%2,%3};"
        : "+f"(c[0]), "+f"(c[1]), "+f"(c[2]), "+f"(c[3])
        : "r"(a[0]), "r"(a[1]), "r"(a[2]), "r"(a[3]), "r"(b[0]), "r"(b[1]));
}
__device__ __forceinline__ void cpasync16(uint32_t d, const void* s) {
    asm volatile("cp.async.cg.shared.global [%0], [%1], 16;" :: "r"(d), "l"(s));
}
__device__ __forceinline__ void cp_commit() { asm volatile("cp.async.commit_group;" ::: "memory"); }
template<int N> __device__ __forceinline__ void cp_wait() {
    asm volatile("cp.async.wait_group %0;" :: "n"(N) : "memory");
}

__device__ __forceinline__ uint32_t pkh(float a, float b) {
    __half2 t = __floats2half2_rn(a, b);
    uint32_t u; memcpy(&u, &t, 4); return u;
}

// load 8 fp32 -> 8 fp16 (16B)
__device__ __forceinline__ uint4 load_h8(const float* p) {
    float4 v0 = *reinterpret_cast<const float4*>(p);
    float4 v1 = *reinterpret_cast<const float4*>(p + 4);
    uint4 o;
    o.x = pkh(v0.x, v0.y); o.y = pkh(v0.z, v0.w);
    o.z = pkh(v1.x, v1.y); o.w = pkh(v1.z, v1.w);
    return o;
}

__device__ __forceinline__ void split1h(float v, __half* h, __half* l) {
    __half hh = __float2half_rn(v);
    *h = hh;
    *l = __float2half_rn(v - __half2float(hh));
}

// ---------------- prep kernels (merged) ----------------
__global__ void prep_lam_kernel(const float* __restrict__ nu_log,
                                const float* __restrict__ th_log,
                                const float* __restrict__ rlog) {
    int i = blockIdx.x * blockDim.x + threadIdx.x;
    if (i < NL*DS) {
        float nu = expf(nu_log[i]);
        float r  = expf(-nu);
        float th = expf(th_log[i]);
        g_lre[i] = r * cosf(th);
        g_lim[i] = r * sinf(th);
        g_gam[i] = sqrtf(fmaxf(1.0f - r*r, 0.0f));
    }
    if (i < NL) g_sres[i] = 1.0f / (1.0f + expf(-rlog[i]));
}

__global__ void prep_wb_enc_kernel(const float* __restrict__ Bre, const float* __restrict__ Bim,
                                   const float* __restrict__ enc_w) {
    int idx = blockIdx.x * blockDim.x + threadIdx.x;
    if (idx < NL*DM*DM) {
        int l = idx / (DM*DM), rem = idx - l*(DM*DM);
        int n = rem / DM, k = rem - n*DM;
        float v;
        if (n < DS) v = g_gam[l*DS + n]      * Bre[((size_t)l*DS + n)*DM + k];
        else        v = g_gam[l*DS + n - DS] * Bim[((size_t)l*DS + (n-DS))*DM + k];
        g_Wb[idx] = __float2half_rn(v);
    } else {
        int e = idx - NL*DM*DM;
        if (e < DM*DIN) split1h(enc_w[e], &g_enchi[e], &g_enclo[e]);
    }
}

__global__ void prep_wc_dec_kernel(const float* __restrict__ Cre, const float* __restrict__ Cim,
                                   const float* __restrict__ dec_w) {
    int idx = blockIdx.x * blockDim.x + threadIdx.x;
    if (idx < NL*DM*DM) {
        int l = idx / (DM*DM), rem = idx - l*(DM*DM);
        int d = rem / DM, k = rem - d*DM;
        float v;
        if (k < DS) v =  Cre[((size_t)l*DM + d)*DS + k];
        else        v = -Cim[((size_t)l*DM + d)*DS + (k-DS)];
        g_Wc[idx] = __float2half_rn(v);
    } else {
        int e = idx - NL*DM*DM;
        if (e < 128*DM) {
            int row = e / DM;
            float v = (row < DOUT) ? dec_w[e] : 0.0f;
            split1h(v, &g_dechi[e], &g_declo[e]);
        }
    }
}

__global__ void prep_wglu_kernel(const float* __restrict__ W1, const float* __restrict__ W2) {
    int idx = blockIdx.x * blockDim.x + threadIdx.x;
    if (idx >= NL*2*DM*DM) return;
    int l = idx / (2*DM*DM), rem = idx - l*(2*DM*DM);
    int n = rem / DM, k = rem - n*DM;
    int o = n >> 1;
    float v = (n & 1) ? W2[((size_t)l*DM + o)*DM + k]
                      : W1[((size_t)l*DM + o)*DM + k];
    g_Wg[idx] = __float2half_rn(v);
}

// ---------------- HMMA GEMM ----------------
// A: fp32 (inline cvt) or fp16 (cp.async, AH). W: fp16 hi(+lo if WLO) via cp.async.
// Stage (32KB): A tile 16KB, W tile 16KB.
// EPI: 0 plain, 1 += Dvec[n]*Xres[m,n], 2 GLU: Xout[m,n/2] += s*even*sigmoid(odd)
// OUTH: store C as fp16 (EPI 0/1).
#define STAGEB 32768

template<bool WLO>
__device__ __forceinline__ void fill_w_async(const __half* __restrict__ Whi,
                                             const __half* __restrict__ Wlo,
                                             int bn, int K, int k0, uint32_t wdst, int tid) {
    if (WLO) {
        const int wrow  = tid >> 1;
        const int whalf = tid & 1;
        const char* src = (const char*)((whalf ? Wlo : Whi) + (size_t)(bn + wrow)*K + k0);
        const uint32_t b0 = (uint32_t)(wrow*128 + whalf*64);
#pragma unroll
        for (int q = 0; q < 4; q++)
            cpasync16(wdst + sw128(b0 + q*16), src + q*16);
    } else {
        const int wrow = tid >> 1;
        const int part = tid & 1;
        const char* src = (const char*)(Whi + (size_t)(bn + wrow)*K + k0 + part*16);
        const uint32_t b0 = (uint32_t)(wrow*128 + part*32);
#pragma unroll
        for (int q = 0; q < 2; q++)
            cpasync16(wdst + sw128(b0 + q*16), src + q*16);
    }
}

__device__ __forceinline__ void fill_a_async(const __half* __restrict__ Ah,
                                             int bm, int K, int k0, uint32_t adst, int tid) {
    const int row  = tid >> 1;      // 0..127
    const int part = tid & 1;       // 64B half of the 128B chunk-row
    const char* src = (const char*)(Ah + (size_t)(bm + row)*K + k0 + part*32);
    const uint32_t b0 = (uint32_t)(row*128 + part*64);
#pragma unroll
    for (int q = 0; q < 4; q++)
        cpasync16(adst + sw128(b0 + q*16), src + q*16);
}

template<int EPI, bool WGUARD, bool WLO, bool AH, bool OUTH>
__global__ __launch_bounds__(256, 2)
void hmma_gemm(const void* __restrict__ Ain,
               const __half* __restrict__ Whi, const __half* __restrict__ Wlo,
               void* __restrict__ Cout, int K, int Ntot,
               const float* __restrict__ Dvec, const float* __restrict__ Xres,
               const float* __restrict__ sres_p, float* __restrict__ Xout) {
    extern __shared__ char smem[];
    const uint32_t s0 = smem_u32(smem);
    const int tid  = threadIdx.x;
    const int wid  = tid >> 5;
    const int lane = tid & 31;
    const int wm   = wid & 1;
    const int wn   = wid >> 1;
    const int bm   = blockIdx.y * 128;
    const int bn   = blockIdx.x * 128;

    const float*  Af = (const float*)Ain;
    const __half* Ah = (const __half*)Ain;

    float acc[4][4][4];
#pragma unroll
    for (int i = 0; i < 4; i++)
#pragma unroll
        for (int j = 0; j < 4; j++)
#pragma unroll
            for (int q = 0; q < 4; q++) acc[i][j][q] = 0.0f;

    const int NK = K >> 5;
    const int frow = tid >> 2;
    const int fq   = tid & 3;

    // prologue: chunk 0 -> buf 0
    fill_w_async<WLO>(Whi, Wlo, bn, K, 0, s0 + 16384, tid);
    uint4 pa0, pa1;
    if (AH) {
        fill_a_async(Ah, bm, K, 0, s0, tid);
        cp_commit();
    } else {
        cp_commit();
        pa0 = load_h8(Af + (size_t)(bm + frow     )*K + fq*8);
        pa1 = load_h8(Af + (size_t)(bm + frow + 64)*K + fq*8);
        *reinterpret_cast<uint4*>(smem + sw128((uint32_t)(frow*128 + fq*16)))      = pa0;
        *reinterpret_cast<uint4*>(smem + sw128((uint32_t)((frow+64)*128 + fq*16))) = pa1;
    }
    cp_wait<0>();
    __syncthreads();

    const int a_row = wm*64 + (lane & 7) + ((lane >> 3) & 1)*8;
    const int a_kb  = (lane >> 4) << 4;
    const int b_sub = lane >> 3;
    const int b_row = wn*32 + (lane & 7) + (b_sub >> 1)*8;
    const int b_kb  = (b_sub & 1) << 4;

    for (int t = 0; t < NK; ++t) {
        const int buf = t & 1;
        if (t + 1 < NK) {
            const int k0 = (t + 1) << 5;
            const uint32_t nb = s0 + (buf ^ 1)*STAGEB;
            fill_w_async<WLO>(Whi, Wlo, bn, K, k0, nb + 16384, tid);
            if (AH) {
                fill_a_async(Ah, bm, K, k0, nb, tid);
                cp_commit();
            } else {
                cp_commit();
                pa0 = load_h8(Af + (size_t)(bm + frow     )*K + k0 + fq*8);
                pa1 = load_h8(Af + (size_t)(bm + frow + 64)*K + k0 + fq*8);
            }
        }
        const uint32_t As = s0 + buf*STAGEB;
        const uint32_t Ws = As + 16384;
#pragma unroll
        for (int s = 0; s < 2; ++s) {
            uint32_t bh[4][2], bl[4][2];
#pragma unroll
            for (int jj = 0; jj < 2; jj++) {
                uint32_t base = (uint32_t)((b_row + 16*jj)*128 + s*32 + b_kb);
                uint32_t r[4];
                ldsm4(r, Ws + sw128(base));
                bh[2*jj][0] = r[0]; bh[2*jj][1] = r[1];
                bh[2*jj+1][0] = r[2]; bh[2*jj+1][1] = r[3];
                if (WLO) {
                    ldsm4(r, Ws + sw128(base + 64));
                    bl[2*jj][0] = r[0]; bl[2*jj][1] = r[1];
                    bl[2*jj+1][0] = r[2]; bl[2*jj+1][1] = r[3];
                }
            }
#pragma unroll
            for (int i = 0; i < 4; i++) {
                uint32_t ah[4];
                uint32_t base = (uint32_t)((a_row + 16*i)*128 + s*32 + a_kb);
                ldsm4(ah, As + sw128(base));
#pragma unroll
                for (int j = 0; j < 4; j++) {
                    mma_f16(acc[i][j], ah, bh[j]);
                    if (WLO) mma_f16(acc[i][j], ah, bl[j]);
                }
            }
        }
        if (t + 1 < NK) {
            if (AH) {
                cp_wait<0>();
                __syncthreads();
            } else {
                char* s2 = smem + (buf ^ 1)*STAGEB;
                __syncthreads();                 // readers done with buf^1
                *reinterpret_cast<uint4*>(s2 + sw128((uint32_t)(frow*128 + fq*16)))      = pa0;
                *reinterpret_cast<uint4*>(s2 + sw128((uint32_t)((frow+64)*128 + fq*16))) = pa1;
                cp_wait<0>();
                __syncthreads();
            }
        }
    }

    // epilogue
    const int gid = lane >> 2;
    const int tg  = lane & 3;
#pragma unroll
    for (int i = 0; i < 4; i++) {
        const int r0 = bm + wm*64 + i*16 + gid;
#pragma unroll
        for (int j = 0; j < 4; j++) {
            const int col = bn + wn*32 + j*8 + tg*2;
            if (EPI == 2) {
                const float s = *sres_p;
                const int oc = col >> 1;
                float* xp0 = Xout + (size_t)r0 * DM + oc;
                float* xp1 = Xout + (size_t)(r0+8) * DM + oc;
                *xp0 = fmaf(s * acc[i][j][0], 1.0f/(1.0f + expf(-acc[i][j][1])), *xp0);
                *xp1 = fmaf(s * acc[i][j][2], 1.0f/(1.0f + expf(-acc[i][j][3])), *xp1);
            } else {
                if (WGUARD && col >= Ntot) continue;
                float2 v0 = make_float2(acc[i][j][0], acc[i][j][1]);
                float2 v1 = make_float2(acc[i][j][2], acc[i][j][3]);
                if (EPI == 1) {
                    const float2 d  = *reinterpret_cast<const float2*>(Dvec + col);
                    const float2 x0 = *reinterpret_cast<const float2*>(Xres + (size_t)r0*Ntot + col);
                    const float2 x1 = *reinterpret_cast<const float2*>(Xres + (size_t)(r0+8)*Ntot + col);
                    v0.x = fmaf(d.x, x0.x, v0.x); v0.y = fmaf(d.y, x0.y, v0.y);
                    v1.x = fmaf(d.x, x1.x, v1.x); v1.y = fmaf(d.y, x1.y, v1.y);
                }
                if (OUTH) {
                    __half2* cp0 = (__half2*)((__half*)Cout + (size_t)r0*Ntot + col);
                    __half2* cp1 = (__half2*)((__half*)Cout + (size_t)(r0+8)*Ntot + col);
                    *cp0 = __floats2half2_rn(v0.x, v0.y);
                    *cp1 = __floats2half2_rn(v1.x, v1.y);
                } else {
                    *reinterpret_cast<float2*>((float*)Cout + (size_t)r0*Ntot + col)     = v0;
                    *reinterpret_cast<float2*>((float*)Cout + (size_t)(r0+8)*Ntot + col) = v1;
                }
            }
        }
    }
}

// ---------------- chunked LRU scan (fp16 Bu/h, fp32 internal) ----------------
__global__ void scan_local_kernel(const __half* __restrict__ Bu, __half* __restrict__ H,
                                  const float* __restrict__ lre_g,
                                  const float* __restrict__ lim_g) {
    int n = threadIdx.x;
    int b = blockIdx.x;
    int c = blockIdx.y;
    float lre = lre_g[n], lim = lim_g[n];
    size_t base = ((size_t)b * LSEQ + (size_t)c * CHLEN) * DM + n;
    float hre = 0.0f, him = 0.0f;
#pragma unroll 4
    for (int t = 0; t < CHLEN; ++t) {
        size_t off = base + (size_t)t * DM;
        float bre = __half2float(Bu[off]);
        float bim = __half2float(Bu[off + DS]);
        float nre = fmaf(lre, hre, fmaf(-lim, him, bre));
        float nim = fmaf(lim, hre, fmaf( lre, him, bim));
        hre = nre; him = nim;
        H[off]      = __float2half_rn(hre);
        H[off + DS] = __float2half_rn(him);
    }
    int ci = b * NCH + c;
    g_cend[(size_t)ci*2*DS + n]      = hre;
    g_cend[(size_t)ci*2*DS + DS + n] = him;
}

// carry + fix merged: each (b, c>=1) block rebuilds its carry-in prefix from g_cend
__global__ void scan_fix_kernel(__half* __restrict__ H,
                                const float* __restrict__ lre_g,
                                const float* __restrict__ lim_g) {
    int n = threadIdx.x;
    int b = blockIdx.x;
    int c = blockIdx.y + 1;
    float lre = lre_g[n], lim = lim_g[n];
    float Pre = lre, Pim = lim;
#pragma unroll
    for (int i = 0; i < 7; i++) {       // lam^128
        float t = Pre*Pre - Pim*Pim;
        Pim = 2.0f*Pre*Pim;
        Pre = t;
    }
    float cre = 0.0f, cim = 0.0f;
    for (int j = 0; j < c; ++j) {
        size_t cj = (size_t)(b * NCH + j) * 2 * DS;
        float ere = g_cend[cj + n];
        float eim = g_cend[cj + DS + n];
        float nre = fmaf(Pre, cre, fmaf(-Pim, cim, ere));
        float nim = fmaf(Pim, cre, fmaf( Pre, cim, eim));
        cre = nre; cim = nim;
    }
    float pre = lre, pim = lim;   // lam^(t+1)
    size_t base = ((size_t)b * LSEQ + (size_t)c * CHLEN) * DM + n;
#pragma unroll 4
    for (int t = 0; t < CHLEN; ++t) {
        size_t off = base + (size_t)t * DM;
        float hre = __half2float(H[off])      + (pre*cre - pim*cim);
        float him = __half2float(H[off + DS]) + (pre*cim + pim*cre);
        H[off]      = __float2half_rn(hre);
        H[off + DS] = __float2half_rn(him);
        float npre = pre*lre - pim*lim;
        float npim = pre*lim + pim*lre;
        pre = npre; pim = npim;
    }
}

// ---------------- host launch ----------------
extern "C" void kernel_launch(void* const* d_in, const int* in_sizes, int n_in,
                              void* d_out, int out_size) {
    const float* u      = (const float*)d_in[0];
    const float* enc_w  = (const float*)d_in[1];
    const float* dec_w  = (const float*)d_in[2];
    const float* nu_log = (const float*)d_in[3];
    const float* th_log = (const float*)d_in[4];
    const float* Bre    = (const float*)d_in[5];
    const float* Bim    = (const float*)d_in[6];
    const float* Cre    = (const float*)d_in[7];
    const float* Cim    = (const float*)d_in[8];
    const float* Dv     = (const float*)d_in[9];
    const float* W1     = (const float*)d_in[10];
    const float* W2     = (const float*)d_in[11];
    const float* rlog   = (const float*)d_in[12];
    float* out = (float*)d_out;

    float *px, *plre, *plim, *psres;
    __half *pbuh, *phh, *pzh;
    __half *pWb, *pWc, *pWg;
    __half *penchi, *penclo, *pdechi, *pdeclo;
    cudaGetSymbolAddress((void**)&px,   g_x);
    cudaGetSymbolAddress((void**)&pbuh, g_buh);
    cudaGetSymbolAddress((void**)&phh,  g_hh);
    cudaGetSymbolAddress((void**)&pzh,  g_zh);
    cudaGetSymbolAddress((void**)&pWb,  g_Wb);
    cudaGetSymbolAddress((void**)&pWc,  g_Wc);
    cudaGetSymbolAddress((void**)&pWg,  g_Wg);
    cudaGetSymbolAddress((void**)&penchi, g_enchi); cudaGetSymbolAddress((void**)&penclo, g_enclo);
    cudaGetSymbolAddress((void**)&pdechi, g_dechi); cudaGetSymbolAddress((void**)&pdeclo, g_declo);
    cudaGetSymbolAddress((void**)&plre,  g_lre);
    cudaGetSymbolAddress((void**)&plim,  g_lim);
    cudaGetSymbolAddress((void**)&psres, g_sres);

    const int SMEM = 2 * STAGEB;   // 64 KB per CTA -> 2 CTAs/SM
    cudaFuncSetAttribute(hmma_gemm<0,false,true ,false,false>, cudaFuncAttributeMaxDynamicSharedMemorySize, SMEM);
    cudaFuncSetAttribute(hmma_gemm<0,false,false,false,true >, cudaFuncAttributeMaxDynamicSharedMemorySize, SMEM);
    cudaFuncSetAttribute(hmma_gemm<1,false,false,true ,true >, cudaFuncAttributeMaxDynamicSharedMemorySize, SMEM);
    cudaFuncSetAttribute(hmma_gemm<2,false,false,true ,false>, cudaFuncAttributeMaxDynamicSharedMemorySize, SMEM);
    cudaFuncSetAttribute(hmma_gemm<0,true ,true ,false,false>, cudaFuncAttributeMaxDynamicSharedMemorySize, SMEM);

    // prep (4 launches)
    prep_lam_kernel   <<<(NL*DS + 255)/256, 256>>>(nu_log, th_log, rlog);
    prep_wb_enc_kernel<<<(NL*DM*DM + DM*DIN + 255)/256, 256>>>(Bre, Bim, enc_w);
    prep_wc_dec_kernel<<<(NL*DM*DM + 128*DM + 255)/256, 256>>>(Cre, Cim, dec_w);
    prep_wglu_kernel  <<<(NL*2*DM*DM + 255)/256, 256>>>(W1, W2);

    // encoder: x = u @ enc_w^T  (fp32 A, hi+lo W, fp32 x out)
    hmma_gemm<0,false,true,false,false><<<dim3(DM/128, MTOK/128), 256, SMEM>>>(
        u, penchi, penclo, px, DIN, DM, nullptr, nullptr, nullptr, nullptr);

    for (int l = 0; l < NL; ++l) {
        const float* lre = plre + l*DS;
        const float* lim = plim + l*DS;
        // Bu = x @ Wb^T -> fp16 Bu
        hmma_gemm<0,false,false,false,true><<<dim3(DM/128, MTOK/128), 256, SMEM>>>(
            px, pWb + (size_t)l*DM*DM, nullptr,
            pbuh, DM, DM, nullptr, nullptr, nullptr, nullptr);
        scan_local_kernel<<<dim3(NB, NCH), DS>>>(pbuh, phh, lre, lim);
        scan_fix_kernel<<<dim3(NB, NCH-1), DS>>>(phh, lre, lim);
        // z = Re(C h) + D*x  (fp16 A=h, fp16 z out)
        hmma_gemm<1,false,false,true,true><<<dim3(DM/128, MTOK/128), 256, SMEM>>>(
            phh, pWc + (size_t)l*DM*DM, nullptr,
            pzh, DM, DM, Dv + l*DM, px, nullptr, nullptr);
        // GLU GEMM (fp16 A=z, N=1024 interleaved): x += s*g1*sigmoid(g2)
        hmma_gemm<2,false,false,true,false><<<dim3(2*DM/128, MTOK/128), 256, SMEM>>>(
            pzh, pWg + (size_t)l*2*DM*DM, nullptr,
            nullptr, DM, 2*DM, nullptr, nullptr, psres + l, px);
    }

    // decoder: out = x @ dec_w^T (fp32 A, hi+lo, N=64 guarded)
    hmma_gemm<0,true,true,false,false><<<dim3(1, MTOK/128), 256, SMEM>>>(
        px, pdechi, pdeclo, out, DM, DOUT, nullptr, nullptr, nullptr, nullptr);
}

// round 13
// speedup vs baseline: 1.7969x; 1.7969x over previous
#include <cuda_runtime.h>
#include <cuda_fp16.h>
#include <math.h>
#include <string.h>
#include <stdint.h>

#define NB    8
#define LSEQ  2048
#define MTOK  (NB*LSEQ)     // 16384 tokens
#define DIN   64
#define DOUT  64
#define DM    512
#define DS    256
#define NL    4
#define NCH   16
#define CHLEN (LSEQ/NCH)    // 128

// ---------------- scratch (device globals; no allocation allowed) ----------------
__device__ float g_x [MTOK*DM];
__device__ float g_bu[MTOK*DM];           // Bu packed [re(256) | im(256)]
__device__ float g_h [MTOK*DM];           // h  packed [re | im]
__device__ float g_z [MTOK*DM];           // LRU output
// weights: single-fp16 for Bu/C/GLU; hi+lo for encoder/decoder
__device__ __half g_Wb  [NL*DM*DM];
__device__ __half g_Wc  [NL*DM*DM];
__device__ __half g_Wg  [NL*2*DM*DM];
__device__ __half g_enchi[DM*DIN],    g_enclo[DM*DIN];
__device__ __half g_dechi[128*DM],    g_declo[128*DM];   // padded to 128 rows
// scan params / carries
__device__ float g_lre[NL*DS], g_lim[NL*DS], g_gam[NL*DS], g_sres[NL];
__device__ float g_cend[NB*NCH*2*DS];

// ---------------- helpers ----------------
__device__ __forceinline__ uint32_t smem_u32(const void* p) {
    uint32_t a;
    asm("{ .reg .u64 t; cvta.to.shared.u64 t, %1; cvt.u32.u64 %0, t; }" : "=r"(a) : "l"(p));
    return a;
}
__device__ __forceinline__ uint32_t sw128(uint32_t b) { return b ^ ((b >> 3) & 0x70); }

__device__ __forceinline__ void ldsm4(uint32_t* r, uint32_t addr) {
    asm volatile("ldmatrix.sync.aligned.m8n8.x4.shared.b16 {%0,%1,%2,%3}, [%4];"
                 : "=r"(r[0]), "=r"(r[1]), "=r"(r[2]), "=r"(r[3]) : "r"(addr));
}
__device__ __forceinline__ void mma_f16(float* c, const uint32_t* a, const uint32_t* b) {
    asm volatile(
        "mma.sync.aligned.m16n8k16.row.col.f32.f16.f16.f32 "
        "{%0,%1,%2,%3}, {%4,%5,%6,%7}, {%8,%9}, {%0,%1,%2,%3};"
        : "+f"(c[0]), "+f"(c[1]), "+f"(c[2]), "+f"(c[3])
        : "r"(a[0]), "r"(a[1]), "r"(a[2]), "r"(a[3]), "r"(b[0]), "r"(b[1]));
}
__device__ __forceinline__ void cpasync16(uint32_t d, const void* s) {
    asm volatile("cp.async.cg.shared.global [%0], [%1], 16;" :: "r"(d), "l"(s));
}
__device__ __forceinline__ void cp_commit() { asm volatile("cp.async.commit_group;" ::: "memory"); }
template<int N> __device__ __forceinline__ void cp_wait() {
    asm volatile("cp.async.wait_group %0;" :: "n"(N) : "memory");
}

__device__ __forceinline__ uint32_t pkh(float a, float b) {
    __half2 t = __floats2half2_rn(a, b);
    uint32_t u; memcpy(&u, &t, 4); return u;
}

// load 8 fp32 -> 8 fp16 (16B)
__device__ __forceinline__ uint4 load_h8(const float* p) {
    float4 v0 = *reinterpret_cast<const float4*>(p);
    float4 v1 = *reinterpret_cast<const float4*>(p + 4);
    uint4 o;
    o.x = pkh(v0.x, v0.y); o.y = pkh(v0.z, v0.w);
    o.z = pkh(v1.x, v1.y); o.w = pkh(v1.z, v1.w);
    return o;
}

__device__ __forceinline__ void split1h(float v, __half* h, __half* l) {
    __half hh = __float2half_rn(v);
    *h = hh;
    *l = __float2half_rn(v - __half2float(hh));
}

// ---------------- prep kernels (merged) ----------------
__global__ void prep_lam_kernel(const float* __restrict__ nu_log,
                                const float* __restrict__ th_log,
                                const float* __restrict__ rlog) {
    int i = blockIdx.x * blockDim.x + threadIdx.x;
    if (i < NL*DS) {
        float nu = expf(nu_log[i]);
        float r  = expf(-nu);
        float th = expf(th_log[i]);
        g_lre[i] = r * cosf(th);
        g_lim[i] = r * sinf(th);
        g_gam[i] = sqrtf(fmaxf(1.0f - r*r, 0.0f));
    }
    if (i < NL) g_sres[i] = 1.0f / (1.0f + expf(-rlog[i]));
}

__global__ void prep_wb_enc_kernel(const float* __restrict__ Bre, const float* __restrict__ Bim,
                                   const float* __restrict__ enc_w) {
    int idx = blockIdx.x * blockDim.x + threadIdx.x;
    if (idx < NL*DM*DM) {
        int l = idx / (DM*DM), rem = idx - l*(DM*DM);
        int n = rem / DM, k = rem - n*DM;
        float v;
        if (n < DS) v = g_gam[l*DS + n]      * Bre[((size_t)l*DS + n)*DM + k];
        else        v = g_gam[l*DS + n - DS] * Bim[((size_t)l*DS + (n-DS))*DM + k];
        g_Wb[idx] = __float2half_rn(v);
    } else {
        int e = idx - NL*DM*DM;
        if (e < DM*DIN) split1h(enc_w[e], &g_enchi[e], &g_enclo[e]);
    }
}

__global__ void prep_wc_dec_kernel(const float* __restrict__ Cre, const float* __restrict__ Cim,
                                   const float* __restrict__ dec_w) {
    int idx = blockIdx.x * blockDim.x + threadIdx.x;
    if (idx < NL*DM*DM) {
        int l = idx / (DM*DM), rem = idx - l*(DM*DM);
        int d = rem / DM, k = rem - d*DM;
        float v;
        if (k < DS) v =  Cre[((size_t)l*DM + d)*DS + k];
        else        v = -Cim[((size_t)l*DM + d)*DS + (k-DS)];
        g_Wc[idx] = __float2half_rn(v);
    } else {
        int e = idx - NL*DM*DM;
        if (e < 128*DM) {
            int row = e / DM;
            float v = (row < DOUT) ? dec_w[e] : 0.0f;
            split1h(v, &g_dechi[e], &g_declo[e]);
        }
    }
}

__global__ void prep_wglu_kernel(const float* __restrict__ W1, const float* __restrict__ W2) {
    int idx = blockIdx.x * blockDim.x + threadIdx.x;
    if (idx >= NL*2*DM*DM) return;
    int l = idx / (2*DM*DM), rem = idx - l*(2*DM*DM);
    int n = rem / DM, k = rem - n*DM;
    int o = n >> 1;
    float v = (n & 1) ? W2[((size_t)l*DM + o)*DM + k]
                      : W1[((size_t)l*DM + o)*DM + k];
    g_Wg[idx] = __float2half_rn(v);
}

// ---------------- HMMA GEMM (R11 structure, known good) ----------------
// A: fp32 -> fp16 inline. W: fp16 hi(+lo if WLO) via cp.async.
// Stage (32KB): A tile 16KB, W tile 16KB.
// EPI: 0 plain, 1 += Dvec[n]*Xres[m,n], 2 GLU: Xout[m,n/2] += s*even*sigmoid(odd)
#define STAGEB 32768

template<bool WLO>
__device__ __forceinline__ void fill_w_async(const __half* __restrict__ Whi,
                                             const __half* __restrict__ Wlo,
                                             int bn, int K, int k0, uint32_t wdst, int tid) {
    if (WLO) {
        const int wrow  = tid >> 1;
        const int whalf = tid & 1;
        const char* src = (const char*)((whalf ? Wlo : Whi) + (size_t)(bn + wrow)*K + k0);
        const uint32_t b0 = (uint32_t)(wrow*128 + whalf*64);
#pragma unroll
        for (int q = 0; q < 4; q++)
            cpasync16(wdst + sw128(b0 + q*16), src + q*16);
    } else {
        const int wrow = tid >> 1;
        const int part = tid & 1;
        const char* src = (const char*)(Whi + (size_t)(bn + wrow)*K + k0 + part*16);
        const uint32_t b0 = (uint32_t)(wrow*128 + part*32);
#pragma unroll
        for (int q = 0; q < 2; q++)
            cpasync16(wdst + sw128(b0 + q*16), src + q*16);
    }
}

template<int EPI, bool WGUARD, bool WLO>
__global__ __launch_bounds__(256, 2)
void hmma_gemm(const float* __restrict__ A,
               const __half* __restrict__ Whi, const __half* __restrict__ Wlo,
               float* __restrict__ C, int K, int Ntot,
               const float* __restrict__ Dvec, const float* __restrict__ Xres,
               const float* __restrict__ sres_p, float* __restrict__ Xout) {
    extern __shared__ char smem[];
    const uint32_t s0 = smem_u32(smem);
    const int tid  = threadIdx.x;
    const int wid  = tid >> 5;
    const int lane = tid & 31;
    const int wm   = wid & 1;
    const int wn   = wid >> 1;
    const int bm   = blockIdx.y * 128;
    const int bn   = blockIdx.x * 128;

    float acc[4][4][4];
#pragma unroll
    for (int i = 0; i < 4; i++)
#pragma unroll
        for (int j = 0; j < 4; j++)
#pragma unroll
            for (int q = 0; q < 4; q++) acc[i][j][q] = 0.0f;

    const int NK = K >> 5;
    const int frow = tid >> 2;
    const int fq   = tid & 3;

    // prologue: chunk 0 -> buf 0
    fill_w_async<WLO>(Whi, Wlo, bn, K, 0, s0 + 16384, tid);
    cp_commit();
    uint4 pa0 = load_h8(A + (size_t)(bm + frow     )*K + fq*8);
    uint4 pa1 = load_h8(A + (size_t)(bm + frow + 64)*K + fq*8);
    *reinterpret_cast<uint4*>(smem + sw128((uint32_t)(frow*128 + fq*16)))        = pa0;
    *reinterpret_cast<uint4*>(smem + sw128((uint32_t)((frow+64)*128 + fq*16)))   = pa1;
    cp_wait<0>();
    __syncthreads();

    const int a_row = wm*64 + (lane & 7) + ((lane >> 3) & 1)*8;
    const int a_kb  = (lane >> 4) << 4;
    const int b_sub = lane >> 3;
    const int b_row = wn*32 + (lane & 7) + (b_sub >> 1)*8;
    const int b_kb  = (b_sub & 1) << 4;

    for (int t = 0; t < NK; ++t) {
        const int buf = t & 1;
        if (t + 1 < NK) {
            const int k0 = (t + 1) << 5;
            fill_w_async<WLO>(Whi, Wlo, bn, K, k0, s0 + (buf ^ 1)*STAGEB + 16384, tid);
            cp_commit();
            pa0 = load_h8(A + (size_t)(bm + frow     )*K + k0 + fq*8);
            pa1 = load_h8(A + (size_t)(bm + frow + 64)*K + k0 + fq*8);
        }
        const uint32_t As = s0 + buf*STAGEB;
        const uint32_t Ws = As + 16384;
#pragma unroll
        for (int s = 0; s < 2; ++s) {
            uint32_t bh[4][2], bl[4][2];
#pragma unroll
            for (int jj = 0; jj < 2; jj++) {
                uint32_t base = (uint32_t)((b_row + 16*jj)*128 + s*32 + b_kb);
                uint32_t r[4];
                ldsm4(r, Ws + sw128(base));
                bh[2*jj][0] = r[0]; bh[2*jj][1] = r[1];
                bh[2*jj+1][0] = r[2]; bh[2*jj+1][1] = r[3];
                if (WLO) {
                    ldsm4(r, Ws + sw128(base + 64));
                    bl[2*jj][0] = r[0]; bl[2*jj][1] = r[1];
                    bl[2*jj+1][0] = r[2]; bl[2*jj+1][1] = r[3];
                }
            }
#pragma unroll
            for (int i = 0; i < 4; i++) {
                uint32_t ah[4];
                uint32_t base = (uint32_t)((a_row + 16*i)*128 + s*32 + a_kb);
                ldsm4(ah, As + sw128(base));
#pragma unroll
                for (int j = 0; j < 4; j++) {
                    mma_f16(acc[i][j], ah, bh[j]);
                    if (WLO) mma_f16(acc[i][j], ah, bl[j]);
                }
            }
        }
        if (t + 1 < NK) {
            char* s2 = smem + (buf ^ 1)*STAGEB;
            __syncthreads();                 // readers done with buf^1
            *reinterpret_cast<uint4*>(s2 + sw128((uint32_t)(frow*128 + fq*16)))      = pa0;
            *reinterpret_cast<uint4*>(s2 + sw128((uint32_t)((frow+64)*128 + fq*16))) = pa1;
            cp_wait<0>();                    // W(t+1) landed
            __syncthreads();                 // buf^1 ready
        }
    }

    // epilogue
    const int gid = lane >> 2;
    const int tg  = lane & 3;
#pragma unroll
    for (int i = 0; i < 4; i++) {
        const int r0 = bm + wm*64 + i*16 + gid;
#pragma unroll
        for (int j = 0; j < 4; j++) {
            const int col = bn + wn*32 + j*8 + tg*2;
            if (EPI == 2) {
                const float s = *sres_p;
                const int oc = col >> 1;
                float* xp0 = Xout + (size_t)r0 * DM + oc;
                float* xp1 = Xout + (size_t)(r0+8) * DM + oc;
                *xp0 = fmaf(s * acc[i][j][0], 1.0f/(1.0f + expf(-acc[i][j][1])), *xp0);
                *xp1 = fmaf(s * acc[i][j][2], 1.0f/(1.0f + expf(-acc[i][j][3])), *xp1);
            } else {
                if (WGUARD && col >= Ntot) continue;
                float2 v0 = make_float2(acc[i][j][0], acc[i][j][1]);
                float2 v1 = make_float2(acc[i][j][2], acc[i][j][3]);
                if (EPI == 1) {
                    const float2 d  = *reinterpret_cast<const float2*>(Dvec + col);
                    const float2 x0 = *reinterpret_cast<const float2*>(Xres + (size_t)r0*Ntot + col);
                    const float2 x1 = *reinterpret_cast<const float2*>(Xres + (size_t)(r0+8)*Ntot + col);
                    v0.x = fmaf(d.x, x0.x, v0.x); v0.y = fmaf(d.y, x0.y, v0.y);
                    v1.x = fmaf(d.x, x1.x, v1.x); v1.y = fmaf(d.y, x1.y, v1.y);
                }
                *reinterpret_cast<float2*>(C + (size_t)r0*Ntot + col)     = v0;
                *reinterpret_cast<float2*>(C + (size_t)(r0+8)*Ntot + col) = v1;
            }
        }
    }
}

// ---------------- two-phase chunked LRU scan (less traffic than local+fix) ----
// Phase A: chunk end-states only (read Bu once, no H writes).
__global__ void scan_ends_kernel(const float* __restrict__ Bu,
                                 const float* __restrict__ lre_g,
                                 const float* __restrict__ lim_g) {
    int n = threadIdx.x;
    int b = blockIdx.x;
    int c = blockIdx.y;
    float lre = lre_g[n], lim = lim_g[n];
    size_t base = ((size_t)b * LSEQ + (size_t)c * CHLEN) * DM + n;
    float hre = 0.0f, him = 0.0f;
#pragma unroll 4
    for (int t = 0; t < CHLEN; ++t) {
        size_t off = base + (size_t)t * DM;
        float bre = Bu[off];
        float bim = Bu[off + DS];
        float nre = fmaf(lre, hre, fmaf(-lim, him, bre));
        float nim = fmaf(lim, hre, fmaf( lre, him, bim));
        hre = nre; him = nim;
    }
    int ci = b * NCH + c;
    g_cend[(size_t)ci*2*DS + n]      = hre;
    g_cend[(size_t)ci*2*DS + DS + n] = him;
}

// Phase B: rebuild carry-in from cend prefix, scan chunk seeded with carry, write H once.
__global__ void scan_apply_kernel(const float* __restrict__ Bu, float* __restrict__ H,
                                  const float* __restrict__ lre_g,
                                  const float* __restrict__ lim_g) {
    int n = threadIdx.x;
    int b = blockIdx.x;
    int c = blockIdx.y;
    float lre = lre_g[n], lim = lim_g[n];
    float Pre = lre, Pim = lim;
#pragma unroll
    for (int i = 0; i < 7; i++) {       // lam^CHLEN, CHLEN = 128
        float t = Pre*Pre - Pim*Pim;
        Pim = 2.0f*Pre*Pim;
        Pre = t;
    }
    float hre = 0.0f, him = 0.0f;       // carry-in = prefix over cend[0..c-1]
    for (int j = 0; j < c; ++j) {
        size_t cj = (size_t)(b * NCH + j) * 2 * DS;
        float ere = g_cend[cj + n];
        float eim = g_cend[cj + DS + n];
        float nre = fmaf(Pre, hre, fmaf(-Pim, him, ere));
        float nim = fmaf(Pim, hre, fmaf( Pre, him, eim));
        hre = nre; him = nim;
    }
    size_t base = ((size_t)b * LSEQ + (size_t)c * CHLEN) * DM + n;
#pragma unroll 4
    for (int t = 0; t < CHLEN; ++t) {
        size_t off = base + (size_t)t * DM;
        float bre = Bu[off];
        float bim = Bu[off + DS];
        float nre = fmaf(lre, hre, fmaf(-lim, him, bre));
        float nim = fmaf(lim, hre, fmaf( lre, him, bim));
        hre = nre; him = nim;
        H[off]      = hre;
        H[off + DS] = him;
    }
}

// ---------------- host launch ----------------
extern "C" void kernel_launch(void* const* d_in, const int* in_sizes, int n_in,
                              void* d_out, int out_size) {
    const float* u      = (const float*)d_in[0];
    const float* enc_w  = (const float*)d_in[1];
    const float* dec_w  = (const float*)d_in[2];
    const float* nu_log = (const float*)d_in[3];
    const float* th_log = (const float*)d_in[4];
    const float* Bre    = (const float*)d_in[5];
    const float* Bim    = (const float*)d_in[6];
    const float* Cre    = (const float*)d_in[7];
    const float* Cim    = (const float*)d_in[8];
    const float* Dv     = (const float*)d_in[9];
    const float* W1     = (const float*)d_in[10];
    const float* W2     = (const float*)d_in[11];
    const float* rlog   = (const float*)d_in[12];
    float* out = (float*)d_out;

    float *px, *pbu, *ph, *pz, *plre, *plim, *psres;
    __half *pWb, *pWc, *pWg;
    __half *penchi, *penclo, *pdechi, *pdeclo;
    cudaGetSymbolAddress((void**)&px,   g_x);
    cudaGetSymbolAddress((void**)&pbu,  g_bu);
    cudaGetSymbolAddress((void**)&ph,   g_h);
    cudaGetSymbolAddress((void**)&pz,   g_z);
    cudaGetSymbolAddress((void**)&pWb,  g_Wb);
    cudaGetSymbolAddress((void**)&pWc,  g_Wc);
    cudaGetSymbolAddress((void**)&pWg,  g_Wg);
    cudaGetSymbolAddress((void**)&penchi, g_enchi); cudaGetSymbolAddress((void**)&penclo, g_enclo);
    cudaGetSymbolAddress((void**)&pdechi, g_dechi); cudaGetSymbolAddress((void**)&pdeclo, g_declo);
    cudaGetSymbolAddress((void**)&plre,  g_lre);
    cudaGetSymbolAddress((void**)&plim,  g_lim);
    cudaGetSymbolAddress((void**)&psres, g_sres);

    const int SMEM = 2 * STAGEB;   // 64 KB per CTA -> 2 CTAs/SM
    cudaFuncSetAttribute(hmma_gemm<0,false,true>,  cudaFuncAttributeMaxDynamicSharedMemorySize, SMEM);
    cudaFuncSetAttribute(hmma_gemm<0,false,false>, cudaFuncAttributeMaxDynamicSharedMemorySize, SMEM);
    cudaFuncSetAttribute(hmma_gemm<1,false,false>, cudaFuncAttributeMaxDynamicSharedMemorySize, SMEM);
    cudaFuncSetAttribute(hmma_gemm<2,false,false>, cudaFuncAttributeMaxDynamicSharedMemorySize, SMEM);
    cudaFuncSetAttribute(hmma_gemm<0,true,true>,   cudaFuncAttributeMaxDynamicSharedMemorySize, SMEM);

    // prep (4 launches)
    prep_lam_kernel   <<<(NL*DS + 255)/256, 256>>>(nu_log, th_log, rlog);
    prep_wb_enc_kernel<<<(NL*DM*DM + DM*DIN + 255)/256, 256>>>(Bre, Bim, enc_w);
    prep_wc_dec_kernel<<<(NL*DM*DM + 128*DM + 255)/256, 256>>>(Cre, Cim, dec_w);
    prep_wglu_kernel  <<<(NL*2*DM*DM + 255)/256, 256>>>(W1, W2);

    // encoder: x = u @ enc_w^T  (K=64, hi+lo)
    hmma_gemm<0,false,true><<<dim3(DM/128, MTOK/128), 256, SMEM>>>(
        u, penchi, penclo, px, DIN, DM, nullptr, nullptr, nullptr, nullptr);

    for (int l = 0; l < NL; ++l) {
        const float* lre = plre + l*DS;
        const float* lim = plim + l*DS;
        // Bu = x @ Wb^T (gamma folded, single-fp16 W)
        hmma_gemm<0,false,false><<<dim3(DM/128, MTOK/128), 256, SMEM>>>(
            px, pWb + (size_t)l*DM*DM, nullptr,
            pbu, DM, DM, nullptr, nullptr, nullptr, nullptr);
        // two-phase scan
        scan_ends_kernel <<<dim3(NB, NCH), DS>>>(pbu, lre, lim);
        scan_apply_kernel<<<dim3(NB, NCH), DS>>>(pbu, ph, lre, lim);
        // z = Re(C h) + D*x (single-fp16 W)
        hmma_gemm<1,false,false><<<dim3(DM/128, MTOK/128), 256, SMEM>>>(
            ph, pWc + (size_t)l*DM*DM, nullptr,
            pz, DM, DM, Dv + l*DM, px, nullptr, nullptr);
        // GLU GEMM (N=1024 interleaved, single-fp16 W): x += s*g1*sigmoid(g2)
        hmma_gemm<2,false,false><<<dim3(2*DM/128, MTOK/128), 256, SMEM>>>(
            pz, pWg + (size_t)l*2*DM*DM, nullptr,
            nullptr, DM, 2*DM, nullptr, nullptr, psres + l, px);
    }

    // decoder: out = x @ dec_w^T (N=64 guarded; hi+lo, padded to 128 rows)
    hmma_gemm<0,true,true><<<dim3(1, MTOK/128), 256, SMEM>>>(
        px, pdechi, pdeclo, out, DM, DOUT, nullptr, nullptr, nullptr, nullptr);
}

// round 14
// speedup vs baseline: 1.9554x; 1.0882x over previous
#include <cuda_runtime.h>
#include <cuda_fp16.h>
#include <math.h>
#include <string.h>
#include <stdint.h>

#define NB    8
#define LSEQ  2048
#define MTOK  (NB*LSEQ)     // 16384 tokens
#define DIN   64
#define DOUT  64
#define DM    512
#define DS    256
#define NL    4
#define NCH   16
#define CHLEN (LSEQ/NCH)    // 128

// ---------------- scratch (device globals; no allocation allowed) ----------------
__device__ float  g_x [MTOK*DM];
__device__ float  g_bu[MTOK*DM];          // Bu packed [re(256) | im(256)] fp32
__device__ float  g_h [MTOK*DM];          // h  packed [re | im] fp32
__device__ __half g_zh[MTOK*DM];          // LRU output, fp16
// weights: single-fp16 for Bu/C/GLU; hi+lo for encoder/decoder
__device__ __half g_Wb  [NL*DM*DM];
__device__ __half g_Wc  [NL*DM*DM];
__device__ __half g_Wg  [NL*2*DM*DM];
__device__ __half g_enchi[DM*DIN],    g_enclo[DM*DIN];
__device__ __half g_dechi[128*DM],    g_declo[128*DM];   // padded to 128 rows
// scan params / carries
__device__ float g_lre[NL*DS], g_lim[NL*DS], g_gam[NL*DS], g_sres[NL];
__device__ float g_cend[NB*NCH*2*DS];

// ---------------- helpers ----------------
__device__ __forceinline__ uint32_t smem_u32(const void* p) {
    uint32_t a;
    asm("{ .reg .u64 t; cvta.to.shared.u64 t, %1; cvt.u32.u64 %0, t; }" : "=r"(a) : "l"(p));
    return a;
}
__device__ __forceinline__ uint32_t sw128(uint32_t b) { return b ^ ((b >> 3) & 0x70); }

__device__ __forceinline__ void ldsm4(uint32_t* r, uint32_t addr) {
    asm volatile("ldmatrix.sync.aligned.m8n8.x4.shared.b16 {%0,%1,%2,%3}, [%4];"
                 : "=r"(r[0]), "=r"(r[1]), "=r"(r[2]), "=r"(r[3]) : "r"(addr));
}
__device__ __forceinline__ void mma_f16(float* c, const uint32_t* a, const uint32_t* b) {
    asm volatile(
        "mma.sync.aligned.m16n8k16.row.col.f32.f16.f16.f32 "
        "{%0,%1,%2,%3}, {%4,%5,%6,%7}, {%8,%9}, {%0,%1,%2,%3};"
        : "+f"(c[0]), "+f"(c[1]), "+f"(c[2]), "+f"(c[3])
        : "r"(a[0]), "r"(a[1]), "r"(a[2]), "r"(a[3]), "r"(b[0]), "r"(b[1]));
}
__device__ __forceinline__ void cpasync16(uint32_t d, const void* s) {
    asm volatile("cp.async.cg.shared.global [%0], [%1], 16;" :: "r"(d), "l"(s));
}
__device__ __forceinline__ void cp_commit() { asm volatile("cp.async.commit_group;" ::: "memory"); }
template<int N> __device__ __forceinline__ void cp_wait() {
    asm volatile("cp.async.wait_group %0;" :: "n"(N) : "memory");
}

__device__ __forceinline__ uint32_t pkh(float a, float b) {
    __half2 t = __floats2half2_rn(a, b);
    uint32_t u; memcpy(&u, &t, 4); return u;
}

// load 8 fp32 -> 8 fp16 (16B)
__device__ __forceinline__ uint4 load_h8(const float* p) {
    float4 v0 = *reinterpret_cast<const float4*>(p);
    float4 v1 = *reinterpret_cast<const float4*>(p + 4);
    uint4 o;
    o.x = pkh(v0.x, v0.y); o.y = pkh(v0.z, v0.w);
    o.z = pkh(v1.x, v1.y); o.w = pkh(v1.z, v1.w);
    return o;
}

__device__ __forceinline__ void split1h(float v, __half* h, __half* l) {
    __half hh = __float2half_rn(v);
    *h = hh;
    *l = __float2half_rn(v - __half2float(hh));
}

// ---------------- prep kernels (merged) ----------------
__global__ void prep_lam_kernel(const float* __restrict__ nu_log,
                                const float* __restrict__ th_log,
                                const float* __restrict__ rlog) {
    int i = blockIdx.x * blockDim.x + threadIdx.x;
    if (i < NL*DS) {
        float nu = expf(nu_log[i]);
        float r  = expf(-nu);
        float th = expf(th_log[i]);
        g_lre[i] = r * cosf(th);
        g_lim[i] = r * sinf(th);
        g_gam[i] = sqrtf(fmaxf(1.0f - r*r, 0.0f));
    }
    if (i < NL) g_sres[i] = 1.0f / (1.0f + expf(-rlog[i]));
}

__global__ void prep_wb_enc_kernel(const float* __restrict__ Bre, const float* __restrict__ Bim,
                                   const float* __restrict__ enc_w) {
    int idx = blockIdx.x * blockDim.x + threadIdx.x;
    if (idx < NL*DM*DM) {
        int l = idx / (DM*DM), rem = idx - l*(DM*DM);
        int n = rem / DM, k = rem - n*DM;
        float v;
        if (n < DS) v = g_gam[l*DS + n]      * Bre[((size_t)l*DS + n)*DM + k];
        else        v = g_gam[l*DS + n - DS] * Bim[((size_t)l*DS + (n-DS))*DM + k];
        g_Wb[idx] = __float2half_rn(v);
    } else {
        int e = idx - NL*DM*DM;
        if (e < DM*DIN) split1h(enc_w[e], &g_enchi[e], &g_enclo[e]);
    }
}

__global__ void prep_wc_dec_kernel(const float* __restrict__ Cre, const float* __restrict__ Cim,
                                   const float* __restrict__ dec_w) {
    int idx = blockIdx.x * blockDim.x + threadIdx.x;
    if (idx < NL*DM*DM) {
        int l = idx / (DM*DM), rem = idx - l*(DM*DM);
        int d = rem / DM, k = rem - d*DM;
        float v;
        if (k < DS) v =  Cre[((size_t)l*DM + d)*DS + k];
        else        v = -Cim[((size_t)l*DM + d)*DS + (k-DS)];
        g_Wc[idx] = __float2half_rn(v);
    } else {
        int e = idx - NL*DM*DM;
        if (e < 128*DM) {
            int row = e / DM;
            float v = (row < DOUT) ? dec_w[e] : 0.0f;
            split1h(v, &g_dechi[e], &g_declo[e]);
        }
    }
}

__global__ void prep_wglu_kernel(const float* __restrict__ W1, const float* __restrict__ W2) {
    int idx = blockIdx.x * blockDim.x + threadIdx.x;
    if (idx >= NL*2*DM*DM) return;
    int l = idx / (2*DM*DM), rem = idx - l*(2*DM*DM);
    int n = rem / DM, k = rem - n*DM;
    int o = n >> 1;
    float v = (n & 1) ? W2[((size_t)l*DM + o)*DM + k]
                      : W1[((size_t)l*DM + o)*DM + k];
    g_Wg[idx] = __float2half_rn(v);
}

// ---------------- HMMA GEMM ----------------
// A: fp32 (inline cvt) or fp16 (cp.async, AH). W: fp16 hi(+lo if WLO) via cp.async.
// EPI: 0 plain, 1 += Dvec[n]*Xres[m,n], 2 GLU: Xout[m,n/2] += s*even*sigmoid(odd)
// OUTH: store C as fp16 (EPI 0/1).
#define STAGEB 32768

template<bool WLO>
__device__ __forceinline__ void fill_w_async(const __half* __restrict__ Whi,
                                             const __half* __restrict__ Wlo,
                                             int bn, int K, int k0, uint32_t wdst, int tid) {
    if (WLO) {
        const int wrow  = tid >> 1;
        const int whalf = tid & 1;
        const char* src = (const char*)((whalf ? Wlo : Whi) + (size_t)(bn + wrow)*K + k0);
        const uint32_t b0 = (uint32_t)(wrow*128 + whalf*64);
#pragma unroll
        for (int q = 0; q < 4; q++)
            cpasync16(wdst + sw128(b0 + q*16), src + q*16);
    } else {
        const int wrow = tid >> 1;
        const int part = tid & 1;
        const char* src = (const char*)(Whi + (size_t)(bn + wrow)*K + k0 + part*16);
        const uint32_t b0 = (uint32_t)(wrow*128 + part*32);
#pragma unroll
        for (int q = 0; q < 2; q++)
            cpasync16(wdst + sw128(b0 + q*16), src + q*16);
    }
}

// A fp16 fill: 128 rows x 64B (32 fp16) per chunk, row stride 128B in smem
__device__ __forceinline__ void fill_a_async(const __half* __restrict__ Ah,
                                             int bm, int K, int k0, uint32_t adst, int tid) {
    const int row  = tid >> 1;      // 0..127
    const int part = tid & 1;       // 32B half of the 64B chunk-row
    const char* src = (const char*)(Ah + (size_t)(bm + row)*K + k0 + part*16);
    const uint32_t b0 = (uint32_t)(row*128 + part*32);
#pragma unroll
    for (int q = 0; q < 2; q++)
        cpasync16(adst + sw128(b0 + q*16), src + q*16);
}

template<int EPI, bool WGUARD, bool WLO, bool AH, bool OUTH>
__global__ __launch_bounds__(256, 2)
void hmma_gemm(const void* __restrict__ Ain,
               const __half* __restrict__ Whi, const __half* __restrict__ Wlo,
               void* __restrict__ Cout, int K, int Ntot,
               const float* __restrict__ Dvec, const float* __restrict__ Xres,
               const float* __restrict__ sres_p, float* __restrict__ Xout) {
    extern __shared__ char smem[];
    const uint32_t s0 = smem_u32(smem);
    const int tid  = threadIdx.x;
    const int wid  = tid >> 5;
    const int lane = tid & 31;
    const int wm   = wid & 1;
    const int wn   = wid >> 1;
    const int bm   = blockIdx.y * 128;
    const int bn   = blockIdx.x * 128;

    const float*  Af = (const float*)Ain;
    const __half* Ah = (const __half*)Ain;

    float acc[4][4][4];
#pragma unroll
    for (int i = 0; i < 4; i++)
#pragma unroll
        for (int j = 0; j < 4; j++)
#pragma unroll
            for (int q = 0; q < 4; q++) acc[i][j][q] = 0.0f;

    const int NK = K >> 5;
    const int frow = tid >> 2;
    const int fq   = tid & 3;

    // prologue: chunk 0 -> buf 0
    fill_w_async<WLO>(Whi, Wlo, bn, K, 0, s0 + 16384, tid);
    uint4 pa0, pa1;
    if (AH) {
        fill_a_async(Ah, bm, K, 0, s0, tid);
        cp_commit();
    } else {
        cp_commit();
        pa0 = load_h8(Af + (size_t)(bm + frow     )*K + fq*8);
        pa1 = load_h8(Af + (size_t)(bm + frow + 64)*K + fq*8);
        *reinterpret_cast<uint4*>(smem + sw128((uint32_t)(frow*128 + fq*16)))      = pa0;
        *reinterpret_cast<uint4*>(smem + sw128((uint32_t)((frow+64)*128 + fq*16))) = pa1;
    }
    cp_wait<0>();
    __syncthreads();

    const int a_row = wm*64 + (lane & 7) + ((lane >> 3) & 1)*8;
    const int a_kb  = (lane >> 4) << 4;
    const int b_sub = lane >> 3;
    const int b_row = wn*32 + (lane & 7) + (b_sub >> 1)*8;
    const int b_kb  = (b_sub & 1) << 4;

    for (int t = 0; t < NK; ++t) {
        const int buf = t & 1;
        if (t + 1 < NK) {
            const int k0 = (t + 1) << 5;
            const uint32_t nb = s0 + (buf ^ 1)*STAGEB;
            fill_w_async<WLO>(Whi, Wlo, bn, K, k0, nb + 16384, tid);
            if (AH) {
                fill_a_async(Ah, bm, K, k0, nb, tid);
                cp_commit();
            } else {
                cp_commit();
                pa0 = load_h8(Af + (size_t)(bm + frow     )*K + k0 + fq*8);
                pa1 = load_h8(Af + (size_t)(bm + frow + 64)*K + k0 + fq*8);
            }
        }
        const uint32_t As = s0 + buf*STAGEB;
        const uint32_t Ws = As + 16384;
#pragma unroll
        for (int s = 0; s < 2; ++s) {
            uint32_t bh[4][2], bl[4][2];
#pragma unroll
            for (int jj = 0; jj < 2; jj++) {
                uint32_t base = (uint32_t)((b_row + 16*jj)*128 + s*32 + b_kb);
                uint32_t r[4];
                ldsm4(r, Ws + sw128(base));
                bh[2*jj][0] = r[0]; bh[2*jj][1] = r[1];
                bh[2*jj+1][0] = r[2]; bh[2*jj+1][1] = r[3];
                if (WLO) {
                    ldsm4(r, Ws + sw128(base + 64));
                    bl[2*jj][0] = r[0]; bl[2*jj][1] = r[1];
                    bl[2*jj+1][0] = r[2]; bl[2*jj+1][1] = r[3];
                }
            }
#pragma unroll
            for (int i = 0; i < 4; i++) {
                uint32_t ah[4];
                uint32_t base = (uint32_t)((a_row + 16*i)*128 + s*32 + a_kb);
                ldsm4(ah, As + sw128(base));
#pragma unroll
                for (int j = 0; j < 4; j++) {
                    mma_f16(acc[i][j], ah, bh[j]);
                    if (WLO) mma_f16(acc[i][j], ah, bl[j]);
                }
            }
        }
        if (t + 1 < NK) {
            if (AH) {
                cp_wait<0>();
                __syncthreads();
            } else {
                char* s2 = smem + (buf ^ 1)*STAGEB;
                __syncthreads();                 // readers done with buf^1
                *reinterpret_cast<uint4*>(s2 + sw128((uint32_t)(frow*128 + fq*16)))      = pa0;
                *reinterpret_cast<uint4*>(s2 + sw128((uint32_t)((frow+64)*128 + fq*16))) = pa1;
                cp_wait<0>();                    // W(t+1) landed
                __syncthreads();                 // buf^1 ready
            }
        }
    }

    // epilogue
    const int gid = lane >> 2;
    const int tg  = lane & 3;
#pragma unroll
    for (int i = 0; i < 4; i++) {
        const int r0 = bm + wm*64 + i*16 + gid;
#pragma unroll
        for (int j = 0; j < 4; j++) {
            const int col = bn + wn*32 + j*8 + tg*2;
            if (EPI == 2) {
                const float s = *sres_p;
                const int oc = col >> 1;
                float* xp0 = Xout + (size_t)r0 * DM + oc;
                float* xp1 = Xout + (size_t)(r0+8) * DM + oc;
                *xp0 = fmaf(s * acc[i][j][0], 1.0f/(1.0f + expf(-acc[i][j][1])), *xp0);
                *xp1 = fmaf(s * acc[i][j][2], 1.0f/(1.0f + expf(-acc[i][j][3])), *xp1);
            } else {
                if (WGUARD && col >= Ntot) continue;
                float2 v0 = make_float2(acc[i][j][0], acc[i][j][1]);
                float2 v1 = make_float2(acc[i][j][2], acc[i][j][3]);
                if (EPI == 1) {
                    const float2 d  = *reinterpret_cast<const float2*>(Dvec + col);
                    const float2 x0 = *reinterpret_cast<const float2*>(Xres + (size_t)r0*Ntot + col);
                    const float2 x1 = *reinterpret_cast<const float2*>(Xres + (size_t)(r0+8)*Ntot + col);
                    v0.x = fmaf(d.x, x0.x, v0.x); v0.y = fmaf(d.y, x0.y, v0.y);
                    v1.x = fmaf(d.x, x1.x, v1.x); v1.y = fmaf(d.y, x1.y, v1.y);
                }
                if (OUTH) {
                    __half2* cp0 = (__half2*)((__half*)Cout + (size_t)r0*Ntot + col);
                    __half2* cp1 = (__half2*)((__half*)Cout + (size_t)(r0+8)*Ntot + col);
                    *cp0 = __floats2half2_rn(v0.x, v0.y);
                    *cp1 = __floats2half2_rn(v1.x, v1.y);
                } else {
                    *reinterpret_cast<float2*>((float*)Cout + (size_t)r0*Ntot + col)     = v0;
                    *reinterpret_cast<float2*>((float*)Cout + (size_t)(r0+8)*Ntot + col) = v1;
                }
            }
        }
    }
}

// ---------------- two-phase chunked LRU scan (fp32, known good) ----------------
__global__ void scan_ends_kernel(const float* __restrict__ Bu,
                                 const float* __restrict__ lre_g,
                                 const float* __restrict__ lim_g) {
    int n = threadIdx.x;
    int b = blockIdx.x;
    int c = blockIdx.y;
    float lre = lre_g[n], lim = lim_g[n];
    size_t base = ((size_t)b * LSEQ + (size_t)c * CHLEN) * DM + n;
    float hre = 0.0f, him = 0.0f;
#pragma unroll 4
    for (int t = 0; t < CHLEN; ++t) {
        size_t off = base + (size_t)t * DM;
        float bre = Bu[off];
        float bim = Bu[off + DS];
        float nre = fmaf(lre, hre, fmaf(-lim, him, bre));
        float nim = fmaf(lim, hre, fmaf( lre, him, bim));
        hre = nre; him = nim;
    }
    int ci = b * NCH + c;
    g_cend[(size_t)ci*2*DS + n]      = hre;
    g_cend[(size_t)ci*2*DS + DS + n] = him;
}

__global__ void scan_apply_kernel(const float* __restrict__ Bu, float* __restrict__ H,
                                  const float* __restrict__ lre_g,
                                  const float* __restrict__ lim_g) {
    int n = threadIdx.x;
    int b = blockIdx.x;
    int c = blockIdx.y;
    float lre = lre_g[n], lim = lim_g[n];
    float Pre = lre, Pim = lim;
#pragma unroll
    for (int i = 0; i < 7; i++) {       // lam^CHLEN
        float t = Pre*Pre - Pim*Pim;
        Pim = 2.0f*Pre*Pim;
        Pre = t;
    }
    float hre = 0.0f, him = 0.0f;
    for (int j = 0; j < c; ++j) {
        size_t cj = (size_t)(b * NCH + j) * 2 * DS;
        float ere = g_cend[cj + n];
        float eim = g_cend[cj + DS + n];
        float nre = fmaf(Pre, hre, fmaf(-Pim, him, ere));
        float nim = fmaf(Pim, hre, fmaf( Pre, him, eim));
        hre = nre; him = nim;
    }
    size_t base = ((size_t)b * LSEQ + (size_t)c * CHLEN) * DM + n;
#pragma unroll 4
    for (int t = 0; t < CHLEN; ++t) {
        size_t off = base + (size_t)t * DM;
        float bre = Bu[off];
        float bim = Bu[off + DS];
        float nre = fmaf(lre, hre, fmaf(-lim, him, bre));
        float nim = fmaf(lim, hre, fmaf( lre, him, bim));
        hre = nre; him = nim;
        H[off]      = hre;
        H[off + DS] = him;
    }
}

// ---------------- host launch ----------------
extern "C" void kernel_launch(void* const* d_in, const int* in_sizes, int n_in,
                              void* d_out, int out_size) {
    const float* u      = (const float*)d_in[0];
    const float* enc_w  = (const float*)d_in[1];
    const float* dec_w  = (const float*)d_in[2];
    const float* nu_log = (const float*)d_in[3];
    const float* th_log = (const float*)d_in[4];
    const float* Bre    = (const float*)d_in[5];
    const float* Bim    = (const float*)d_in[6];
    const float* Cre    = (const float*)d_in[7];
    const float* Cim    = (const float*)d_in[8];
    const float* Dv     = (const float*)d_in[9];
    const float* W1     = (const float*)d_in[10];
    const float* W2     = (const float*)d_in[11];
    const float* rlog   = (const float*)d_in[12];
    float* out = (float*)d_out;

    float *px, *pbu, *ph, *plre, *plim, *psres;
    __half *pzh, *pWb, *pWc, *pWg;
    __half *penchi, *penclo, *pdechi, *pdeclo;
    cudaGetSymbolAddress((void**)&px,   g_x);
    cudaGetSymbolAddress((void**)&pbu,  g_bu);
    cudaGetSymbolAddress((void**)&ph,   g_h);
    cudaGetSymbolAddress((void**)&pzh,  g_zh);
    cudaGetSymbolAddress((void**)&pWb,  g_Wb);
    cudaGetSymbolAddress((void**)&pWc,  g_Wc);
    cudaGetSymbolAddress((void**)&pWg,  g_Wg);
    cudaGetSymbolAddress((void**)&penchi, g_enchi); cudaGetSymbolAddress((void**)&penclo, g_enclo);
    cudaGetSymbolAddress((void**)&pdechi, g_dechi); cudaGetSymbolAddress((void**)&pdeclo, g_declo);
    cudaGetSymbolAddress((void**)&plre,  g_lre);
    cudaGetSymbolAddress((void**)&plim,  g_lim);
    cudaGetSymbolAddress((void**)&psres, g_sres);

    const int SMEM = 2 * STAGEB;   // 64 KB per CTA -> 2 CTAs/SM
    cudaFuncSetAttribute(hmma_gemm<0,false,true ,false,false>, cudaFuncAttributeMaxDynamicSharedMemorySize, SMEM);
    cudaFuncSetAttribute(hmma_gemm<0,false,false,false,false>, cudaFuncAttributeMaxDynamicSharedMemorySize, SMEM);
    cudaFuncSetAttribute(hmma_gemm<1,false,false,false,true >, cudaFuncAttributeMaxDynamicSharedMemorySize, SMEM);
    cudaFuncSetAttribute(hmma_gemm<2,false,false,true ,false>, cudaFuncAttributeMaxDynamicSharedMemorySize, SMEM);
    cudaFuncSetAttribute(hmma_gemm<0,true ,true ,false,false>, cudaFuncAttributeMaxDynamicSharedMemorySize, SMEM);

    // prep (4 launches; prep_wglu is the clock-state sentinel)
    prep_lam_kernel   <<<(NL*DS + 255)/256, 256>>>(nu_log, th_log, rlog);
    prep_wb_enc_kernel<<<(NL*DM*DM + DM*DIN + 255)/256, 256>>>(Bre, Bim, enc_w);
    prep_wc_dec_kernel<<<(NL*DM*DM + 128*DM + 255)/256, 256>>>(Cre, Cim, dec_w);
    prep_wglu_kernel  <<<(NL*2*DM*DM + 255)/256, 256>>>(W1, W2);

    // encoder: x = u @ enc_w^T  (fp32 A, hi+lo W)
    hmma_gemm<0,false,true,false,false><<<dim3(DM/128, MTOK/128), 256, SMEM>>>(
        u, penchi, penclo, px, DIN, DM, nullptr, nullptr, nullptr, nullptr);

    for (int l = 0; l < NL; ++l) {
        const float* lre = plre + l*DS;
        const float* lim = plim + l*DS;
        // Bu = x @ Wb^T (fp32 A, fp32 out)
        hmma_gemm<0,false,false,false,false><<<dim3(DM/128, MTOK/128), 256, SMEM>>>(
            px, pWb + (size_t)l*DM*DM, nullptr,
            pbu, DM, DM, nullptr, nullptr, nullptr, nullptr);
        // two-phase scan (fp32)
        scan_ends_kernel <<<dim3(NB, NCH), DS>>>(pbu, lre, lim);
        scan_apply_kernel<<<dim3(NB, NCH), DS>>>(pbu, ph, lre, lim);
        // z = Re(C h) + D*x (fp32 A=h, fp16 z out)
        hmma_gemm<1,false,false,false,true><<<dim3(DM/128, MTOK/128), 256, SMEM>>>(
            ph, pWc + (size_t)l*DM*DM, nullptr,
            pzh, DM, DM, Dv + l*DM, px, nullptr, nullptr);
        // GLU GEMM (fp16 A=z via cp.async): x += s*g1*sigmoid(g2)
        hmma_gemm<2,false,false,true,false><<<dim3(2*DM/128, MTOK/128), 256, SMEM>>>(
            pzh, pWg + (size_t)l*2*DM*DM, nullptr,
            nullptr, DM, 2*DM, nullptr, nullptr, psres + l, px);
    }

    // decoder: out = x @ dec_w^T (fp32 A, hi+lo, N=64 guarded)
    hmma_gemm<0,true,true,false,false><<<dim3(1, MTOK/128), 256, SMEM>>>(
        px, pdechi, pdeclo, out, DM, DOUT, nullptr, nullptr, nullptr, nullptr);
}

// round 15
// speedup vs baseline: 2.0306x; 1.0385x over previous
#include <cuda_runtime.h>
#include <cuda_fp16.h>
#include <math.h>
#include <string.h>
#include <stdint.h>

#define NB    8
#define LSEQ  2048
#define MTOK  (NB*LSEQ)     // 16384 tokens
#define DIN   64
#define DOUT  64
#define DM    512
#define DS    256
#define NL    4
#define NCH   16
#define CHLEN (LSEQ/NCH)    // 128

// ---------------- scratch (device globals; no allocation allowed) ----------------
__device__ float  g_x  [MTOK*DM];         // fp32 residual stream
__device__ __half g_buh[MTOK*DM];         // fp16 Bu packed [re|im]
__device__ __half g_hh [MTOK*DM];         // fp16 h  packed [re|im]
__device__ __half g_zh [MTOK*DM];         // fp16 LRU output
// weights: single-fp16 for Bu/C/GLU; hi+lo for encoder/decoder
__device__ __half g_Wb  [NL*DM*DM];
__device__ __half g_Wc  [NL*DM*DM];
__device__ __half g_Wg  [NL*2*DM*DM];
__device__ __half g_enchi[DM*DIN],    g_enclo[DM*DIN];
__device__ __half g_dechi[128*DM],    g_declo[128*DM];   // padded to 128 rows
// scan params / carries
__device__ float g_lre[NL*DS], g_lim[NL*DS], g_gam[NL*DS], g_sres[NL];
__device__ float g_cend[NB*NCH*2*DS];

// ---------------- helpers ----------------
__device__ __forceinline__ uint32_t smem_u32(const void* p) {
    uint32_t a;
    asm("{ .reg .u64 t; cvta.to.shared.u64 t, %1; cvt.u32.u64 %0, t; }" : "=r"(a) : "l"(p));
    return a;
}
__device__ __forceinline__ uint32_t sw128(uint32_t b) { return b ^ ((b >> 3) & 0x70); }

__device__ __forceinline__ void ldsm4(uint32_t* r, uint32_t addr) {
    asm volatile("ldmatrix.sync.aligned.m8n8.x4.shared.b16 {%0,%1,%2,%3}, [%4];"
                 : "=r"(r[0]), "=r"(r[1]), "=r"(r[2]), "=r"(r[3]) : "r"(addr));
}
__device__ __forceinline__ void mma_f16(float* c, const uint32_t* a, const uint32_t* b) {
    asm volatile(
        "mma.sync.aligned.m16n8k16.row.col.f32.f16.f16.f32 "
        "{%0,%1,%2,%3}, {%4,%5,%6,%7}, {%8,%9}, {%0,%1,%2,%3};"
        : "+f"(c[0]), "+f"(c[1]), "+f"(c[2]), "+f"(c[3])
        : "r"(a[0]), "r"(a[1]), "r"(a[2]), "r"(a[3]), "r"(b[0]), "r"(b[1]));
}
__device__ __forceinline__ void cpasync16(uint32_t d, const void* s) {
    asm volatile("cp.async.cg.shared.global [%0], [%1], 16;" :: "r"(d), "l"(s));
}
__device__ __forceinline__ void cp_commit() { asm volatile("cp.async.commit_group;" ::: "memory"); }
template<int N> __device__ __forceinline__ void cp_wait() {
    asm volatile("cp.async.wait_group %0;" :: "n"(N) : "memory");
}

__device__ __forceinline__ uint32_t pkh(float a, float b) {
    __half2 t = __floats2half2_rn(a, b);
    uint32_t u; memcpy(&u, &t, 4); return u;
}

// load 8 fp32 -> 8 fp16 (16B)
__device__ __forceinline__ uint4 load_h8(const float* p) {
    float4 v0 = *reinterpret_cast<const float4*>(p);
    float4 v1 = *reinterpret_cast<const float4*>(p + 4);
    uint4 o;
    o.x = pkh(v0.x, v0.y); o.y = pkh(v0.z, v0.w);
    o.z = pkh(v1.x, v1.y); o.w = pkh(v1.z, v1.w);
    return o;
}

__device__ __forceinline__ void split1h(float v, __half* h, __half* l) {
    __half hh = __float2half_rn(v);
    *h = hh;
    *l = __float2half_rn(v - __half2float(hh));
}

// ---------------- prep kernels (merged) ----------------
__global__ void prep_lam_kernel(const float* __restrict__ nu_log,
                                const float* __restrict__ th_log,
                                const float* __restrict__ rlog) {
    int i = blockIdx.x * blockDim.x + threadIdx.x;
    if (i < NL*DS) {
        float nu = expf(nu_log[i]);
        float r  = expf(-nu);
        float th = expf(th_log[i]);
        g_lre[i] = r * cosf(th);
        g_lim[i] = r * sinf(th);
        g_gam[i] = sqrtf(fmaxf(1.0f - r*r, 0.0f));
    }
    if (i < NL) g_sres[i] = 1.0f / (1.0f + expf(-rlog[i]));
}

__global__ void prep_wb_enc_kernel(const float* __restrict__ Bre, const float* __restrict__ Bim,
                                   const float* __restrict__ enc_w) {
    int idx = blockIdx.x * blockDim.x + threadIdx.x;
    if (idx < NL*DM*DM) {
        int l = idx / (DM*DM), rem = idx - l*(DM*DM);
        int n = rem / DM, k = rem - n*DM;
        float v;
        if (n < DS) v = g_gam[l*DS + n]      * Bre[((size_t)l*DS + n)*DM + k];
        else        v = g_gam[l*DS + n - DS] * Bim[((size_t)l*DS + (n-DS))*DM + k];
        g_Wb[idx] = __float2half_rn(v);
    } else {
        int e = idx - NL*DM*DM;
        if (e < DM*DIN) split1h(enc_w[e], &g_enchi[e], &g_enclo[e]);
    }
}

__global__ void prep_wc_dec_kernel(const float* __restrict__ Cre, const float* __restrict__ Cim,
                                   const float* __restrict__ dec_w) {
    int idx = blockIdx.x * blockDim.x + threadIdx.x;
    if (idx < NL*DM*DM) {
        int l = idx / (DM*DM), rem = idx - l*(DM*DM);
        int d = rem / DM, k = rem - d*DM;
        float v;
        if (k < DS) v =  Cre[((size_t)l*DM + d)*DS + k];
        else        v = -Cim[((size_t)l*DM + d)*DS + (k-DS)];
        g_Wc[idx] = __float2half_rn(v);
    } else {
        int e = idx - NL*DM*DM;
        if (e < 128*DM) {
            int row = e / DM;
            float v = (row < DOUT) ? dec_w[e] : 0.0f;
            split1h(v, &g_dechi[e], &g_declo[e]);
        }
    }
}

__global__ void prep_wglu_kernel(const float* __restrict__ W1, const float* __restrict__ W2) {
    int idx = blockIdx.x * blockDim.x + threadIdx.x;
    if (idx >= NL*2*DM*DM) return;
    int l = idx / (2*DM*DM), rem = idx - l*(2*DM*DM);
    int n = rem / DM, k = rem - n*DM;
    int o = n >> 1;
    float v = (n & 1) ? W2[((size_t)l*DM + o)*DM + k]
                      : W1[((size_t)l*DM + o)*DM + k];
    g_Wg[idx] = __float2half_rn(v);
}

// ---------------- HMMA GEMM ----------------
// A: fp32 (inline cvt) or fp16 (cp.async, AH). W: fp16 hi(+lo if WLO) via cp.async.
// EPI: 0 plain, 1 += Dvec[n]*Xres[m,n], 2 GLU: Xout[m,n/2] += s*even*sigmoid(odd)
// OUTH: store C as fp16 (EPI 0/1).
#define STAGEB 32768

template<bool WLO>
__device__ __forceinline__ void fill_w_async(const __half* __restrict__ Whi,
                                             const __half* __restrict__ Wlo,
                                             int bn, int K, int k0, uint32_t wdst, int tid) {
    if (WLO) {
        const int wrow  = tid >> 1;
        const int whalf = tid & 1;
        const char* src = (const char*)((whalf ? Wlo : Whi) + (size_t)(bn + wrow)*K + k0);
        const uint32_t b0 = (uint32_t)(wrow*128 + whalf*64);
#pragma unroll
        for (int q = 0; q < 4; q++)
            cpasync16(wdst + sw128(b0 + q*16), src + q*16);
    } else {
        const int wrow = tid >> 1;
        const int part = tid & 1;
        const char* src = (const char*)(Whi + (size_t)(bn + wrow)*K + k0 + part*16);
        const uint32_t b0 = (uint32_t)(wrow*128 + part*32);
#pragma unroll
        for (int q = 0; q < 2; q++)
            cpasync16(wdst + sw128(b0 + q*16), src + q*16);
    }
}

// A fp16 fill: 128 rows x 64B (32 fp16) per chunk
__device__ __forceinline__ void fill_a_async(const __half* __restrict__ Ah,
                                             int bm, int K, int k0, uint32_t adst, int tid) {
    const int row  = tid >> 1;      // 0..127
    const int part = tid & 1;       // 32B half of the 64B chunk-row
    const char* src = (const char*)(Ah + (size_t)(bm + row)*K + k0 + part*16);
    const uint32_t b0 = (uint32_t)(row*128 + part*32);
#pragma unroll
    for (int q = 0; q < 2; q++)
        cpasync16(adst + sw128(b0 + q*16), src + q*16);
}

template<int EPI, bool WGUARD, bool WLO, bool AH, bool OUTH>
__global__ __launch_bounds__(256, 2)
void hmma_gemm(const void* __restrict__ Ain,
               const __half* __restrict__ Whi, const __half* __restrict__ Wlo,
               void* __restrict__ Cout, int K, int Ntot,
               const float* __restrict__ Dvec, const float* __restrict__ Xres,
               const float* __restrict__ sres_p, float* __restrict__ Xout) {
    extern __shared__ char smem[];
    const uint32_t s0 = smem_u32(smem);
    const int tid  = threadIdx.x;
    const int wid  = tid >> 5;
    const int lane = tid & 31;
    const int wm   = wid & 1;
    const int wn   = wid >> 1;
    const int bm   = blockIdx.y * 128;
    const int bn   = blockIdx.x * 128;

    const float*  Af = (const float*)Ain;
    const __half* Ah = (const __half*)Ain;

    float acc[4][4][4];
#pragma unroll
    for (int i = 0; i < 4; i++)
#pragma unroll
        for (int j = 0; j < 4; j++)
#pragma unroll
            for (int q = 0; q < 4; q++) acc[i][j][q] = 0.0f;

    const int NK = K >> 5;
    const int frow = tid >> 2;
    const int fq   = tid & 3;

    // prologue: chunk 0 -> buf 0
    fill_w_async<WLO>(Whi, Wlo, bn, K, 0, s0 + 16384, tid);
    uint4 pa0, pa1;
    if (AH) {
        fill_a_async(Ah, bm, K, 0, s0, tid);
        cp_commit();
    } else {
        cp_commit();
        pa0 = load_h8(Af + (size_t)(bm + frow     )*K + fq*8);
        pa1 = load_h8(Af + (size_t)(bm + frow + 64)*K + fq*8);
        *reinterpret_cast<uint4*>(smem + sw128((uint32_t)(frow*128 + fq*16)))      = pa0;
        *reinterpret_cast<uint4*>(smem + sw128((uint32_t)((frow+64)*128 + fq*16))) = pa1;
    }
    cp_wait<0>();
    __syncthreads();

    const int a_row = wm*64 + (lane & 7) + ((lane >> 3) & 1)*8;
    const int a_kb  = (lane >> 4) << 4;
    const int b_sub = lane >> 3;
    const int b_row = wn*32 + (lane & 7) + (b_sub >> 1)*8;
    const int b_kb  = (b_sub & 1) << 4;

    for (int t = 0; t < NK; ++t) {
        const int buf = t & 1;
        if (t + 1 < NK) {
            const int k0 = (t + 1) << 5;
            const uint32_t nb = s0 + (buf ^ 1)*STAGEB;
            fill_w_async<WLO>(Whi, Wlo, bn, K, k0, nb + 16384, tid);
            if (AH) {
                fill_a_async(Ah, bm, K, k0, nb, tid);
                cp_commit();
            } else {
                cp_commit();
                pa0 = load_h8(Af + (size_t)(bm + frow     )*K + k0 + fq*8);
                pa1 = load_h8(Af + (size_t)(bm + frow + 64)*K + k0 + fq*8);
            }
        }
        const uint32_t As = s0 + buf*STAGEB;
        const uint32_t Ws = As + 16384;
#pragma unroll
        for (int s = 0; s < 2; ++s) {
            uint32_t bh[4][2], bl[4][2];
#pragma unroll
            for (int jj = 0; jj < 2; jj++) {
                uint32_t base = (uint32_t)((b_row + 16*jj)*128 + s*32 + b_kb);
                uint32_t r[4];
                ldsm4(r, Ws + sw128(base));
                bh[2*jj][0] = r[0]; bh[2*jj][1] = r[1];
                bh[2*jj+1][0] = r[2]; bh[2*jj+1][1] = r[3];
                if (WLO) {
                    ldsm4(r, Ws + sw128(base + 64));
                    bl[2*jj][0] = r[0]; bl[2*jj][1] = r[1];
                    bl[2*jj+1][0] = r[2]; bl[2*jj+1][1] = r[3];
                }
            }
#pragma unroll
            for (int i = 0; i < 4; i++) {
                uint32_t ah[4];
                uint32_t base = (uint32_t)((a_row + 16*i)*128 + s*32 + a_kb);
                ldsm4(ah, As + sw128(base));
#pragma unroll
                for (int j = 0; j < 4; j++) {
                    mma_f16(acc[i][j], ah, bh[j]);
                    if (WLO) mma_f16(acc[i][j], ah, bl[j]);
                }
            }
        }
        if (t + 1 < NK) {
            if (AH) {
                cp_wait<0>();
                __syncthreads();
            } else {
                char* s2 = smem + (buf ^ 1)*STAGEB;
                __syncthreads();                 // readers done with buf^1
                *reinterpret_cast<uint4*>(s2 + sw128((uint32_t)(frow*128 + fq*16)))      = pa0;
                *reinterpret_cast<uint4*>(s2 + sw128((uint32_t)((frow+64)*128 + fq*16))) = pa1;
                cp_wait<0>();                    // W(t+1) landed
                __syncthreads();                 // buf^1 ready
            }
        }
    }

    // epilogue
    const int gid = lane >> 2;
    const int tg  = lane & 3;
#pragma unroll
    for (int i = 0; i < 4; i++) {
        const int r0 = bm + wm*64 + i*16 + gid;
#pragma unroll
        for (int j = 0; j < 4; j++) {
            const int col = bn + wn*32 + j*8 + tg*2;
            if (EPI == 2) {
                const float s = *sres_p;
                const int oc = col >> 1;
                float* xp0 = Xout + (size_t)r0 * DM + oc;
                float* xp1 = Xout + (size_t)(r0+8) * DM + oc;
                *xp0 = fmaf(s * acc[i][j][0], 1.0f/(1.0f + expf(-acc[i][j][1])), *xp0);
                *xp1 = fmaf(s * acc[i][j][2], 1.0f/(1.0f + expf(-acc[i][j][3])), *xp1);
            } else {
                if (WGUARD && col >= Ntot) continue;
                float2 v0 = make_float2(acc[i][j][0], acc[i][j][1]);
                float2 v1 = make_float2(acc[i][j][2], acc[i][j][3]);
                if (EPI == 1) {
                    const float2 d  = *reinterpret_cast<const float2*>(Dvec + col);
                    const float2 x0 = *reinterpret_cast<const float2*>(Xres + (size_t)r0*Ntot + col);
                    const float2 x1 = *reinterpret_cast<const float2*>(Xres + (size_t)(r0+8)*Ntot + col);
                    v0.x = fmaf(d.x, x0.x, v0.x); v0.y = fmaf(d.y, x0.y, v0.y);
                    v1.x = fmaf(d.x, x1.x, v1.x); v1.y = fmaf(d.y, x1.y, v1.y);
                }
                if (OUTH) {
                    __half2* cp0 = (__half2*)((__half*)Cout + (size_t)r0*Ntot + col);
                    __half2* cp1 = (__half2*)((__half*)Cout + (size_t)(r0+8)*Ntot + col);
                    *cp0 = __floats2half2_rn(v0.x, v0.y);
                    *cp1 = __floats2half2_rn(v1.x, v1.y);
                } else {
                    *reinterpret_cast<float2*>((float*)Cout + (size_t)r0*Ntot + col)     = v0;
                    *reinterpret_cast<float2*>((float*)Cout + (size_t)(r0+8)*Ntot + col) = v1;
                }
            }
        }
    }
}

// ---------------- two-phase chunked LRU scan (fp16 I/O, fp32 internal) --------
__global__ void scan_ends_kernel(const __half* __restrict__ Bu,
                                 const float* __restrict__ lre_g,
                                 const float* __restrict__ lim_g) {
    int n = threadIdx.x;
    int b = blockIdx.x;
    int c = blockIdx.y;
    float lre = lre_g[n], lim = lim_g[n];
    size_t base = ((size_t)b * LSEQ + (size_t)c * CHLEN) * DM + n;
    float hre = 0.0f, him = 0.0f;
#pragma unroll 4
    for (int t = 0; t < CHLEN; ++t) {
        size_t off = base + (size_t)t * DM;
        float bre = __half2float(Bu[off]);
        float bim = __half2float(Bu[off + DS]);
        float nre = fmaf(lre, hre, fmaf(-lim, him, bre));
        float nim = fmaf(lim, hre, fmaf( lre, him, bim));
        hre = nre; him = nim;
    }
    int ci = b * NCH + c;
    g_cend[(size_t)ci*2*DS + n]      = hre;
    g_cend[(size_t)ci*2*DS + DS + n] = him;
}

__global__ void scan_apply_kernel(const __half* __restrict__ Bu, __half* __restrict__ H,
                                  const float* __restrict__ lre_g,
                                  const float* __restrict__ lim_g) {
    int n = threadIdx.x;
    int b = blockIdx.x;
    int c = blockIdx.y;
    float lre = lre_g[n], lim = lim_g[n];
    float Pre = lre, Pim = lim;
#pragma unroll
    for (int i = 0; i < 7; i++) {       // lam^CHLEN
        float t = Pre*Pre - Pim*Pim;
        Pim = 2.0f*Pre*Pim;
        Pre = t;
    }
    float hre = 0.0f, him = 0.0f;       // carry-in = prefix over cend[0..c-1]
    for (int j = 0; j < c; ++j) {
        size_t cj = (size_t)(b * NCH + j) * 2 * DS;
        float ere = g_cend[cj + n];
        float eim = g_cend[cj + DS + n];
        float nre = fmaf(Pre, hre, fmaf(-Pim, him, ere));
        float nim = fmaf(Pim, hre, fmaf( Pre, him, eim));
        hre = nre; him = nim;
    }
    size_t base = ((size_t)b * LSEQ + (size_t)c * CHLEN) * DM + n;
#pragma unroll 4
    for (int t = 0; t < CHLEN; ++t) {
        size_t off = base + (size_t)t * DM;
        float bre = __half2float(Bu[off]);
        float bim = __half2float(Bu[off + DS]);
        float nre = fmaf(lre, hre, fmaf(-lim, him, bre));
        float nim = fmaf(lim, hre, fmaf( lre, him, bim));
        hre = nre; him = nim;
        H[off]      = __float2half_rn(hre);
        H[off + DS] = __float2half_rn(him);
    }
}

// ---------------- host launch ----------------
extern "C" void kernel_launch(void* const* d_in, const int* in_sizes, int n_in,
                              void* d_out, int out_size) {
    const float* u      = (const float*)d_in[0];
    const float* enc_w  = (const float*)d_in[1];
    const float* dec_w  = (const float*)d_in[2];
    const float* nu_log = (const float*)d_in[3];
    const float* th_log = (const float*)d_in[4];
    const float* Bre    = (const float*)d_in[5];
    const float* Bim    = (const float*)d_in[6];
    const float* Cre    = (const float*)d_in[7];
    const float* Cim    = (const float*)d_in[8];
    const float* Dv     = (const float*)d_in[9];
    const float* W1     = (const float*)d_in[10];
    const float* W2     = (const float*)d_in[11];
    const float* rlog   = (const float*)d_in[12];
    float* out = (float*)d_out;

    float *px, *plre, *plim, *psres;
    __half *pbuh, *phh, *pzh, *pWb, *pWc, *pWg;
    __half *penchi, *penclo, *pdechi, *pdeclo;
    cudaGetSymbolAddress((void**)&px,   g_x);
    cudaGetSymbolAddress((void**)&pbuh, g_buh);
    cudaGetSymbolAddress((void**)&phh,  g_hh);
    cudaGetSymbolAddress((void**)&pzh,  g_zh);
    cudaGetSymbolAddress((void**)&pWb,  g_Wb);
    cudaGetSymbolAddress((void**)&pWc,  g_Wc);
    cudaGetSymbolAddress((void**)&pWg,  g_Wg);
    cudaGetSymbolAddress((void**)&penchi, g_enchi); cudaGetSymbolAddress((void**)&penclo, g_enclo);
    cudaGetSymbolAddress((void**)&pdechi, g_dechi); cudaGetSymbolAddress((void**)&pdeclo, g_declo);
    cudaGetSymbolAddress((void**)&plre,  g_lre);
    cudaGetSymbolAddress((void**)&plim,  g_lim);
    cudaGetSymbolAddress((void**)&psres, g_sres);

    const int SMEM = 2 * STAGEB;   // 64 KB per CTA -> 2 CTAs/SM
    cudaFuncSetAttribute(hmma_gemm<0,false,true ,false,false>, cudaFuncAttributeMaxDynamicSharedMemorySize, SMEM);
    cudaFuncSetAttribute(hmma_gemm<0,false,false,false,true >, cudaFuncAttributeMaxDynamicSharedMemorySize, SMEM);
    cudaFuncSetAttribute(hmma_gemm<1,false,false,true ,true >, cudaFuncAttributeMaxDynamicSharedMemorySize, SMEM);
    cudaFuncSetAttribute(hmma_gemm<2,false,false,true ,false>, cudaFuncAttributeMaxDynamicSharedMemorySize, SMEM);
    cudaFuncSetAttribute(hmma_gemm<0,true ,true ,false,false>, cudaFuncAttributeMaxDynamicSharedMemorySize, SMEM);

    // prep (4 launches; prep_wglu is the clock-state sentinel)
    prep_lam_kernel   <<<(NL*DS + 255)/256, 256>>>(nu_log, th_log, rlog);
    prep_wb_enc_kernel<<<(NL*DM*DM + DM*DIN + 255)/256, 256>>>(Bre, Bim, enc_w);
    prep_wc_dec_kernel<<<(NL*DM*DM + 128*DM + 255)/256, 256>>>(Cre, Cim, dec_w);
    prep_wglu_kernel  <<<(NL*2*DM*DM + 255)/256, 256>>>(W1, W2);

    // encoder: x = u @ enc_w^T  (fp32 A, hi+lo W)
    hmma_gemm<0,false,true,false,false><<<dim3(DM/128, MTOK/128), 256, SMEM>>>(
        u, penchi, penclo, px, DIN, DM, nullptr, nullptr, nullptr, nullptr);

    for (int l = 0; l < NL; ++l) {
        const float* lre = plre + l*DS;
        const float* lim = plim + l*DS;
        // Bu = x @ Wb^T (fp32 A, fp16 out)
        hmma_gemm<0,false,false,false,true><<<dim3(DM/128, MTOK/128), 256, SMEM>>>(
            px, pWb + (size_t)l*DM*DM, nullptr,
            pbuh, DM, DM, nullptr, nullptr, nullptr, nullptr);
        // two-phase scan (fp16 I/O, fp32 internal)
        scan_ends_kernel <<<dim3(NB, NCH), DS>>>(pbuh, lre, lim);
        scan_apply_kernel<<<dim3(NB, NCH), DS>>>(pbuh, phh, lre, lim);
        // z = Re(C h) + D*x (fp16 A=h via cp.async, fp16 z out)
        hmma_gemm<1,false,false,true,true><<<dim3(DM/128, MTOK/128), 256, SMEM>>>(
            phh, pWc + (size_t)l*DM*DM, nullptr,
            pzh, DM, DM, Dv + l*DM, px, nullptr, nullptr);
        // GLU GEMM (fp16 A=z via cp.async): x += s*g1*sigmoid(g2)
        hmma_gemm<2,false,false,true,false><<<dim3(2*DM/128, MTOK/128), 256, SMEM>>>(
            pzh, pWg + (size_t)l*2*DM*DM, nullptr,
            nullptr, DM, 2*DM, nullptr, nullptr, psres + l, px);
    }

    // decoder: out = x @ dec_w^T (fp32 A, hi+lo, N=64 guarded)
    hmma_gemm<0,true,true,false,false><<<dim3(1, MTOK/128), 256, SMEM>>>(
        px, pdechi, pdeclo, out, DM, DOUT, nullptr, nullptr, nullptr, nullptr);
}

// round 16
// speedup vs baseline: 2.0332x; 1.0013x over previous
#include <cuda_runtime.h>
#include <cuda_fp16.h>
#include <math.h>
#include <string.h>
#include <stdint.h>

#define NB    8
#define LSEQ  2048
#define MTOK  (NB*LSEQ)     // 16384 tokens
#define DIN   64
#define DOUT  64
#define DM    512
#define DS    256
#define NL    4
#define NCH   16
#define CHLEN (LSEQ/NCH)    // 128

// ---------------- scratch (device globals; no allocation allowed) ----------------
__device__ float  g_x  [MTOK*DM];         // fp32 residual stream
__device__ __half g_xh [MTOK*DM];         // fp16 shadow of x (bit-identical to in-loop cvt)
__device__ __half g_buh[MTOK*DM];         // fp16 Bu packed [re|im]
__device__ __half g_hh [MTOK*DM];         // fp16 h  packed [re|im]
__device__ __half g_zh [MTOK*DM];         // fp16 LRU output
// weights: single-fp16 for Bu/C/GLU; hi+lo for encoder/decoder
__device__ __half g_Wb  [NL*DM*DM];
__device__ __half g_Wc  [NL*DM*DM];
__device__ __half g_Wg  [NL*2*DM*DM];
__device__ __half g_enchi[DM*DIN],    g_enclo[DM*DIN];
__device__ __half g_dechi[128*DM],    g_declo[128*DM];   // padded to 128 rows
// scan params / carries
__device__ float g_lre[NL*DS], g_lim[NL*DS], g_sres[NL];
__device__ float g_cend[NB*NCH*2*DS];

// ---------------- helpers ----------------
__device__ __forceinline__ uint32_t smem_u32(const void* p) {
    uint32_t a;
    asm("{ .reg .u64 t; cvta.to.shared.u64 t, %1; cvt.u32.u64 %0, t; }" : "=r"(a) : "l"(p));
    return a;
}
__device__ __forceinline__ uint32_t sw128(uint32_t b) { return b ^ ((b >> 3) & 0x70); }

__device__ __forceinline__ void ldsm4(uint32_t* r, uint32_t addr) {
    asm volatile("ldmatrix.sync.aligned.m8n8.x4.shared.b16 {%0,%1,%2,%3}, [%4];"
                 : "=r"(r[0]), "=r"(r[1]), "=r"(r[2]), "=r"(r[3]) : "r"(addr));
}
__device__ __forceinline__ void mma_f16(float* c, const uint32_t* a, const uint32_t* b) {
    asm volatile(
        "mma.sync.aligned.m16n8k16.row.col.f32.f16.f16.f32 "
        "{%0,%1,%2,%3}, {%4,%5,%6,%7}, {%8,%9}, {%0,%1,%2,%3};"
        : "+f"(c[0]), "+f"(c[1]), "+f"(c[2]), "+f"(c[3])
        : "r"(a[0]), "r"(a[1]), "r"(a[2]), "r"(a[3]), "r"(b[0]), "r"(b[1]));
}
__device__ __forceinline__ void cpasync16(uint32_t d, const void* s) {
    asm volatile("cp.async.cg.shared.global [%0], [%1], 16;" :: "r"(d), "l"(s));
}
__device__ __forceinline__ void cp_commit() { asm volatile("cp.async.commit_group;" ::: "memory"); }
template<int N> __device__ __forceinline__ void cp_wait() {
    asm volatile("cp.async.wait_group %0;" :: "n"(N) : "memory");
}

__device__ __forceinline__ uint32_t pkh(float a, float b) {
    __half2 t = __floats2half2_rn(a, b);
    uint32_t u; memcpy(&u, &t, 4); return u;
}

// load 8 fp32 -> 8 fp16 (16B)
__device__ __forceinline__ uint4 load_h8(const float* p) {
    float4 v0 = *reinterpret_cast<const float4*>(p);
    float4 v1 = *reinterpret_cast<const float4*>(p + 4);
    uint4 o;
    o.x = pkh(v0.x, v0.y); o.y = pkh(v0.z, v0.w);
    o.z = pkh(v1.x, v1.y); o.w = pkh(v1.z, v1.w);
    return o;
}

__device__ __forceinline__ void split1h(float v, __half* h, __half* l) {
    __half hh = __float2half_rn(v);
    *h = hh;
    *l = __float2half_rn(v - __half2float(hh));
}

// ---------------- prep kernels ----------------
__global__ void prep_lam_kernel(const float* __restrict__ nu_log,
                                const float* __restrict__ th_log,
                                const float* __restrict__ rlog) {
    int i = blockIdx.x * blockDim.x + threadIdx.x;
    if (i < NL*DS) {
        float nu = expf(nu_log[i]);
        float r  = expf(-nu);
        float th = expf(th_log[i]);
        g_lre[i] = r * cosf(th);
        g_lim[i] = r * sinf(th);
    }
    if (i < NL) g_sres[i] = 1.0f / (1.0f + expf(-rlog[i]));
}

// single merged weight prep (gamma recomputed inline; new clock sentinel)
#define PW_WB   (NL*DM*DM)
#define PW_ENC  (PW_WB + DM*DIN)
#define PW_WC   (PW_ENC + NL*DM*DM)
#define PW_DEC  (PW_WC + 128*DM)
#define PW_WG   (PW_DEC + NL*2*DM*DM)

__global__ void prep_weights_kernel(const float* __restrict__ Bre, const float* __restrict__ Bim,
                                    const float* __restrict__ enc_w,
                                    const float* __restrict__ Cre, const float* __restrict__ Cim,
                                    const float* __restrict__ dec_w,
                                    const float* __restrict__ W1, const float* __restrict__ W2,
                                    const float* __restrict__ nu_log) {
    int idx = blockIdx.x * blockDim.x + threadIdx.x;
    if (idx < PW_WB) {
        int l = idx / (DM*DM), rem = idx - l*(DM*DM);
        int n = rem / DM, k = rem - n*DM;
        int ns = (n < DS) ? n : n - DS;
        float r = expf(-expf(nu_log[l*DS + ns]));
        float gam = sqrtf(fmaxf(1.0f - r*r, 0.0f));
        float v = gam * ((n < DS) ? Bre[((size_t)l*DS + n)*DM + k]
                                  : Bim[((size_t)l*DS + (n-DS))*DM + k]);
        g_Wb[idx] = __float2half_rn(v);
    } else if (idx < PW_ENC) {
        int e = idx - PW_WB;
        split1h(enc_w[e], &g_enchi[e], &g_enclo[e]);
    } else if (idx < PW_WC) {
        int e = idx - PW_ENC;
        int l = e / (DM*DM), rem = e - l*(DM*DM);
        int d = rem / DM, k = rem - d*DM;
        float v;
        if (k < DS) v =  Cre[((size_t)l*DM + d)*DS + k];
        else        v = -Cim[((size_t)l*DM + d)*DS + (k-DS)];
        g_Wc[e] = __float2half_rn(v);
    } else if (idx < PW_DEC) {
        int e = idx - PW_WC;
        int row = e / DM;
        float v = (row < DOUT) ? dec_w[e] : 0.0f;
        split1h(v, &g_dechi[e], &g_declo[e]);
    } else if (idx < PW_WG) {
        int e = idx - PW_DEC;
        int l = e / (2*DM*DM), rem = e - l*(2*DM*DM);
        int n = rem / DM, k = rem - n*DM;
        int o = n >> 1;
        float v = (n & 1) ? W2[((size_t)l*DM + o)*DM + k]
                          : W1[((size_t)l*DM + o)*DM + k];
        g_Wg[e] = __float2half_rn(v);
    }
}

// ---------------- HMMA GEMM ----------------
// A: fp32 (inline cvt) or fp16 (cp.async, AH). W: fp16 hi(+lo if WLO) via cp.async.
// EPI: 0 plain, 1 += Dvec[n]*Xres[m,n], 2 GLU: Xout[m,n/2] += s*even*sigmoid(odd)
// OUTH: store C fp16. OUTB: store fp32 C + fp16 Chalf (EPI 0); for EPI 2, also
// update fp16 Chalf shadow of Xout.
#define STAGEB 32768

template<bool WLO>
__device__ __forceinline__ void fill_w_async(const __half* __restrict__ Whi,
                                             const __half* __restrict__ Wlo,
                                             int bn, int K, int k0, uint32_t wdst, int tid) {
    if (WLO) {
        const int wrow  = tid >> 1;
        const int whalf = tid & 1;
        const char* src = (const char*)((whalf ? Wlo : Whi) + (size_t)(bn + wrow)*K + k0);
        const uint32_t b0 = (uint32_t)(wrow*128 + whalf*64);
#pragma unroll
        for (int q = 0; q < 4; q++)
            cpasync16(wdst + sw128(b0 + q*16), src + q*16);
    } else {
        const int wrow = tid >> 1;
        const int part = tid & 1;
        const char* src = (const char*)(Whi + (size_t)(bn + wrow)*K + k0 + part*16);
        const uint32_t b0 = (uint32_t)(wrow*128 + part*32);
#pragma unroll
        for (int q = 0; q < 2; q++)
            cpasync16(wdst + sw128(b0 + q*16), src + q*16);
    }
}

// A fp16 fill: 128 rows x 64B (32 fp16) per chunk
__device__ __forceinline__ void fill_a_async(const __half* __restrict__ Ah,
                                             int bm, int K, int k0, uint32_t adst, int tid) {
    const int row  = tid >> 1;
    const int part = tid & 1;
    const char* src = (const char*)(Ah + (size_t)(bm + row)*K + k0 + part*16);
    const uint32_t b0 = (uint32_t)(row*128 + part*32);
#pragma unroll
    for (int q = 0; q < 2; q++)
        cpasync16(adst + sw128(b0 + q*16), src + q*16);
}

template<int EPI, bool WGUARD, bool WLO, bool AH, bool OUTH, bool OUTB>
__global__ __launch_bounds__(256, 2)
void hmma_gemm(const void* __restrict__ Ain,
               const __half* __restrict__ Whi, const __half* __restrict__ Wlo,
               void* __restrict__ Cout, __half* __restrict__ Chalf, int K, int Ntot,
               const float* __restrict__ Dvec, const float* __restrict__ Xres,
               const float* __restrict__ sres_p, float* __restrict__ Xout) {
    extern __shared__ char smem[];
    const uint32_t s0 = smem_u32(smem);
    const int tid  = threadIdx.x;
    const int wid  = tid >> 5;
    const int lane = tid & 31;
    const int wm   = wid & 1;
    const int wn   = wid >> 1;
    const int bm   = blockIdx.y * 128;
    const int bn   = blockIdx.x * 128;

    const float*  Af = (const float*)Ain;
    const __half* Ah = (const __half*)Ain;

    float acc[4][4][4];
#pragma unroll
    for (int i = 0; i < 4; i++)
#pragma unroll
        for (int j = 0; j < 4; j++)
#pragma unroll
            for (int q = 0; q < 4; q++) acc[i][j][q] = 0.0f;

    const int NK = K >> 5;
    const int frow = tid >> 2;
    const int fq   = tid & 3;

    // prologue: chunk 0 -> buf 0
    fill_w_async<WLO>(Whi, Wlo, bn, K, 0, s0 + 16384, tid);
    uint4 pa0, pa1;
    if (AH) {
        fill_a_async(Ah, bm, K, 0, s0, tid);
        cp_commit();
    } else {
        cp_commit();
        pa0 = load_h8(Af + (size_t)(bm + frow     )*K + fq*8);
        pa1 = load_h8(Af + (size_t)(bm + frow + 64)*K + fq*8);
        *reinterpret_cast<uint4*>(smem + sw128((uint32_t)(frow*128 + fq*16)))      = pa0;
        *reinterpret_cast<uint4*>(smem + sw128((uint32_t)((frow+64)*128 + fq*16))) = pa1;
    }
    cp_wait<0>();
    __syncthreads();

    const int a_row = wm*64 + (lane & 7) + ((lane >> 3) & 1)*8;
    const int a_kb  = (lane >> 4) << 4;
    const int b_sub = lane >> 3;
    const int b_row = wn*32 + (lane & 7) + (b_sub >> 1)*8;
    const int b_kb  = (b_sub & 1) << 4;

    for (int t = 0; t < NK; ++t) {
        const int buf = t & 1;
        if (t + 1 < NK) {
            const int k0 = (t + 1) << 5;
            const uint32_t nb = s0 + (buf ^ 1)*STAGEB;
            fill_w_async<WLO>(Whi, Wlo, bn, K, k0, nb + 16384, tid);
            if (AH) {
                fill_a_async(Ah, bm, K, k0, nb, tid);
                cp_commit();
            } else {
                cp_commit();
                pa0 = load_h8(Af + (size_t)(bm + frow     )*K + k0 + fq*8);
                pa1 = load_h8(Af + (size_t)(bm + frow + 64)*K + k0 + fq*8);
            }
        }
        const uint32_t As = s0 + buf*STAGEB;
        const uint32_t Ws = As + 16384;
#pragma unroll
        for (int s = 0; s < 2; ++s) {
            uint32_t bh[4][2], bl[4][2];
#pragma unroll
            for (int jj = 0; jj < 2; jj++) {
                uint32_t base = (uint32_t)((b_row + 16*jj)*128 + s*32 + b_kb);
                uint32_t r[4];
                ldsm4(r, Ws + sw128(base));
                bh[2*jj][0] = r[0]; bh[2*jj][1] = r[1];
                bh[2*jj+1][0] = r[2]; bh[2*jj+1][1] = r[3];
                if (WLO) {
                    ldsm4(r, Ws + sw128(base + 64));
                    bl[2*jj][0] = r[0]; bl[2*jj][1] = r[1];
                    bl[2*jj+1][0] = r[2]; bl[2*jj+1][1] = r[3];
                }
            }
#pragma unroll
            for (int i = 0; i < 4; i++) {
                uint32_t ah[4];
                uint32_t base = (uint32_t)((a_row + 16*i)*128 + s*32 + a_kb);
                ldsm4(ah, As + sw128(base));
#pragma unroll
                for (int j = 0; j < 4; j++) {
                    mma_f16(acc[i][j], ah, bh[j]);
                    if (WLO) mma_f16(acc[i][j], ah, bl[j]);
                }
            }
        }
        if (t + 1 < NK) {
            if (AH) {
                cp_wait<0>();
                __syncthreads();
            } else {
                char* s2 = smem + (buf ^ 1)*STAGEB;
                __syncthreads();
                *reinterpret_cast<uint4*>(s2 + sw128((uint32_t)(frow*128 + fq*16)))      = pa0;
                *reinterpret_cast<uint4*>(s2 + sw128((uint32_t)((frow+64)*128 + fq*16))) = pa1;
                cp_wait<0>();
                __syncthreads();
            }
        }
    }

    // epilogue
    const int gid = lane >> 2;
    const int tg  = lane & 3;
#pragma unroll
    for (int i = 0; i < 4; i++) {
        const int r0 = bm + wm*64 + i*16 + gid;
#pragma unroll
        for (int j = 0; j < 4; j++) {
            const int col = bn + wn*32 + j*8 + tg*2;
            if (EPI == 2) {
                const float s = *sres_p;
                const int oc = col >> 1;
                size_t i0 = (size_t)r0 * DM + oc;
                size_t i1 = (size_t)(r0+8) * DM + oc;
                float x0 = fmaf(s * acc[i][j][0], 1.0f/(1.0f + expf(-acc[i][j][1])), Xout[i0]);
                float x1 = fmaf(s * acc[i][j][2], 1.0f/(1.0f + expf(-acc[i][j][3])), Xout[i1]);
                Xout[i0] = x0; Xout[i1] = x1;
                if (OUTB) {
                    Chalf[i0] = __float2half_rn(x0);
                    Chalf[i1] = __float2half_rn(x1);
                }
            } else {
                if (WGUARD && col >= Ntot) continue;
                float2 v0 = make_float2(acc[i][j][0], acc[i][j][1]);
                float2 v1 = make_float2(acc[i][j][2], acc[i][j][3]);
                if (EPI == 1) {
                    const float2 d  = *reinterpret_cast<const float2*>(Dvec + col);
                    const float2 x0 = *reinterpret_cast<const float2*>(Xres + (size_t)r0*Ntot + col);
                    const float2 x1 = *reinterpret_cast<const float2*>(Xres + (size_t)(r0+8)*Ntot + col);
                    v0.x = fmaf(d.x, x0.x, v0.x); v0.y = fmaf(d.y, x0.y, v0.y);
                    v1.x = fmaf(d.x, x1.x, v1.x); v1.y = fmaf(d.y, x1.y, v1.y);
                }
                size_t i0 = (size_t)r0*Ntot + col;
                size_t i1 = (size_t)(r0+8)*Ntot + col;
                if (OUTH) {
                    *(__half2*)((__half*)Cout + i0) = __floats2half2_rn(v0.x, v0.y);
                    *(__half2*)((__half*)Cout + i1) = __floats2half2_rn(v1.x, v1.y);
                } else {
                    *reinterpret_cast<float2*>((float*)Cout + i0) = v0;
                    *reinterpret_cast<float2*>((float*)Cout + i1) = v1;
                    if (OUTB) {
                        *(__half2*)(Chalf + i0) = __floats2half2_rn(v0.x, v0.y);
                        *(__half2*)(Chalf + i1) = __floats2half2_rn(v1.x, v1.y);
                    }
                }
            }
        }
    }
}

// ---------------- two-phase chunked LRU scan (fp16 I/O, fp32 internal) --------
__global__ void scan_ends_kernel(const __half* __restrict__ Bu,
                                 const float* __restrict__ lre_g,
                                 const float* __restrict__ lim_g) {
    int n = threadIdx.x;
    int b = blockIdx.x;
    int c = blockIdx.y;
    float lre = lre_g[n], lim = lim_g[n];
    size_t base = ((size_t)b * LSEQ + (size_t)c * CHLEN) * DM + n;
    float hre = 0.0f, him = 0.0f;
#pragma unroll 4
    for (int t = 0; t < CHLEN; ++t) {
        size_t off = base + (size_t)t * DM;
        float bre = __half2float(Bu[off]);
        float bim = __half2float(Bu[off + DS]);
        float nre = fmaf(lre, hre, fmaf(-lim, him, bre));
        float nim = fmaf(lim, hre, fmaf( lre, him, bim));
        hre = nre; him = nim;
    }
    int ci = b * NCH + c;
    g_cend[(size_t)ci*2*DS + n]      = hre;
    g_cend[(size_t)ci*2*DS + DS + n] = him;
}

__global__ void scan_apply_kernel(const __half* __restrict__ Bu, __half* __restrict__ H,
                                  const float* __restrict__ lre_g,
                                  const float* __restrict__ lim_g) {
    int n = threadIdx.x;
    int b = blockIdx.x;
    int c = blockIdx.y;
    float lre = lre_g[n], lim = lim_g[n];
    float Pre = lre, Pim = lim;
#pragma unroll
    for (int i = 0; i < 7; i++) {
        float t = Pre*Pre - Pim*Pim;
        Pim = 2.0f*Pre*Pim;
        Pre = t;
    }
    float hre = 0.0f, him = 0.0f;
    for (int j = 0; j < c; ++j) {
        size_t cj = (size_t)(b * NCH + j) * 2 * DS;
        float ere = g_cend[cj + n];
        float eim = g_cend[cj + DS + n];
        float nre = fmaf(Pre, hre, fmaf(-Pim, him, ere));
        float nim = fmaf(Pim, hre, fmaf( Pre, him, eim));
        hre = nre; him = nim;
    }
    size_t base = ((size_t)b * LSEQ + (size_t)c * CHLEN) * DM + n;
#pragma unroll 4
    for (int t = 0; t < CHLEN; ++t) {
        size_t off = base + (size_t)t * DM;
        float bre = __half2float(Bu[off]);
        float bim = __half2float(Bu[off + DS]);
        float nre = fmaf(lre, hre, fmaf(-lim, him, bre));
        float nim = fmaf(lim, hre, fmaf( lre, him, bim));
        hre = nre; him = nim;
        H[off]      = __float2half_rn(hre);
        H[off + DS] = __float2half_rn(him);
    }
}

// ---------------- host launch ----------------
extern "C" void kernel_launch(void* const* d_in, const int* in_sizes, int n_in,
                              void* d_out, int out_size) {
    const float* u      = (const float*)d_in[0];
    const float* enc_w  = (const float*)d_in[1];
    const float* dec_w  = (const float*)d_in[2];
    const float* nu_log = (const float*)d_in[3];
    const float* th_log = (const float*)d_in[4];
    const float* Bre    = (const float*)d_in[5];
    const float* Bim    = (const float*)d_in[6];
    const float* Cre    = (const float*)d_in[7];
    const float* Cim    = (const float*)d_in[8];
    const float* Dv     = (const float*)d_in[9];
    const float* W1     = (const float*)d_in[10];
    const float* W2     = (const float*)d_in[11];
    const float* rlog   = (const float*)d_in[12];
    float* out = (float*)d_out;

    float *px, *plre, *plim, *psres;
    __half *pxh, *pbuh, *phh, *pzh, *pWb, *pWc, *pWg;
    __half *penchi, *penclo, *pdechi, *pdeclo;
    cudaGetSymbolAddress((void**)&px,   g_x);
    cudaGetSymbolAddress((void**)&pxh,  g_xh);
    cudaGetSymbolAddress((void**)&pbuh, g_buh);
    cudaGetSymbolAddress((void**)&phh,  g_hh);
    cudaGetSymbolAddress((void**)&pzh,  g_zh);
    cudaGetSymbolAddress((void**)&pWb,  g_Wb);
    cudaGetSymbolAddress((void**)&pWc,  g_Wc);
    cudaGetSymbolAddress((void**)&pWg,  g_Wg);
    cudaGetSymbolAddress((void**)&penchi, g_enchi); cudaGetSymbolAddress((void**)&penclo, g_enclo);
    cudaGetSymbolAddress((void**)&pdechi, g_dechi); cudaGetSymbolAddress((void**)&pdeclo, g_declo);
    cudaGetSymbolAddress((void**)&plre,  g_lre);
    cudaGetSymbolAddress((void**)&plim,  g_lim);
    cudaGetSymbolAddress((void**)&psres, g_sres);

    const int SMEM = 2 * STAGEB;   // 64 KB per CTA -> 2 CTAs/SM
    cudaFuncSetAttribute(hmma_gemm<0,false,true ,false,false,true >, cudaFuncAttributeMaxDynamicSharedMemorySize, SMEM);
    cudaFuncSetAttribute(hmma_gemm<0,false,false,true ,true ,false>, cudaFuncAttributeMaxDynamicSharedMemorySize, SMEM);
    cudaFuncSetAttribute(hmma_gemm<1,false,false,true ,true ,false>, cudaFuncAttributeMaxDynamicSharedMemorySize, SMEM);
    cudaFuncSetAttribute(hmma_gemm<2,false,false,true ,false,true >, cudaFuncAttributeMaxDynamicSharedMemorySize, SMEM);
    cudaFuncSetAttribute(hmma_gemm<0,true ,true ,true ,false,false>, cudaFuncAttributeMaxDynamicSharedMemorySize, SMEM);

    // prep (2 launches; prep_weights is the clock-state sentinel, ~20us healthy)
    prep_lam_kernel    <<<(NL*DS + 255)/256, 256>>>(nu_log, th_log, rlog);
    prep_weights_kernel<<<(PW_WG + 255)/256, 256>>>(Bre, Bim, enc_w, Cre, Cim, dec_w, W1, W2, nu_log);

    // encoder: x = u @ enc_w^T  (fp32 A, hi+lo W) -> fp32 x + fp16 xh
    hmma_gemm<0,false,true,false,false,true><<<dim3(DM/128, MTOK/128), 256, SMEM>>>(
        u, penchi, penclo, px, pxh, DIN, DM, nullptr, nullptr, nullptr, nullptr);

    for (int l = 0; l < NL; ++l) {
        const float* lre = plre + l*DS;
        const float* lim = plim + l*DS;
        // Bu = xh @ Wb^T (fp16 A via cp.async, fp16 out)
        hmma_gemm<0,false,false,true,true,false><<<dim3(DM/128, MTOK/128), 256, SMEM>>>(
            pxh, pWb + (size_t)l*DM*DM, nullptr,
            pbuh, nullptr, DM, DM, nullptr, nullptr, nullptr, nullptr);
        // two-phase scan (fp16 I/O, fp32 internal)
        scan_ends_kernel <<<dim3(NB, NCH), DS>>>(pbuh, lre, lim);
        scan_apply_kernel<<<dim3(NB, NCH), DS>>>(pbuh, phh, lre, lim);
        // z = Re(C h) + D*x (fp16 A=h via cp.async, fp16 z out; D*x from fp32 x)
        hmma_gemm<1,false,false,true,true,false><<<dim3(DM/128, MTOK/128), 256, SMEM>>>(
            phh, pWc + (size_t)l*DM*DM, nullptr,
            pzh, nullptr, DM, DM, Dv + l*DM, px, nullptr, nullptr);
        // GLU GEMM (fp16 A=z): x += s*g1*sigmoid(g2), update fp32 x + fp16 xh
        hmma_gemm<2,false,false,true,false,true><<<dim3(2*DM/128, MTOK/128), 256, SMEM>>>(
            pzh, pWg + (size_t)l*2*DM*DM, nullptr,
            nullptr, pxh, DM, 2*DM, nullptr, nullptr, psres + l, px);
    }

    // decoder: out = xh @ dec_w^T (fp16 A via cp.async, hi+lo W, N=64 guarded)
    hmma_gemm<0,true,true,true,false,false><<<dim3(1, MTOK/128), 256, SMEM>>>(
        pxh, pdechi, pdeclo, out, nullptr, DM, DOUT, nullptr, nullptr, nullptr, nullptr);
}

// round 17
// speedup vs baseline: 2.0415x; 1.0041x over previous
#include <cuda_runtime.h>
#include <cuda_fp16.h>
#include <math.h>
#include <string.h>
#include <stdint.h>

#define NB    8
#define LSEQ  2048
#define MTOK  (NB*LSEQ)     // 16384 tokens
#define DIN   64
#define DOUT  64
#define DM    512
#define DS    256
#define NL    4
#define NCH   16
#define CHLEN (LSEQ/NCH)    // 128

// ---------------- scratch (device globals; no allocation allowed) ----------------
__device__ float  g_x  [MTOK*DM];         // fp32 residual stream
__device__ __half g_xh [MTOK*DM];         // fp16 shadow of x
__device__ __half g_buh[MTOK*DM];         // fp16 Bu packed [re|im]
__device__ __half g_hh [MTOK*DM];         // fp16 h  packed [re|im]
__device__ __half g_zh [MTOK*DM];         // fp16 LRU output
// weights: single-fp16 for Bu/C/GLU; hi+lo for encoder/decoder
__device__ __half g_Wb  [NL*DM*DM];
__device__ __half g_Wc  [NL*DM*DM];
__device__ __half g_Wg  [NL*2*DM*DM];
__device__ __half g_enchi[DM*DIN],    g_enclo[DM*DIN];
__device__ __half g_dechi[128*DM],    g_declo[128*DM];   // padded to 128 rows
// scan params / carries
__device__ float g_lre[NL*DS], g_lim[NL*DS], g_sres[NL];
__device__ float g_cend[NB*NCH*2*DS];

// ---------------- helpers ----------------
__device__ __forceinline__ uint32_t smem_u32(const void* p) {
    uint32_t a;
    asm("{ .reg .u64 t; cvta.to.shared.u64 t, %1; cvt.u32.u64 %0, t; }" : "=r"(a) : "l"(p));
    return a;
}
__device__ __forceinline__ uint32_t sw128(uint32_t b) { return b ^ ((b >> 3) & 0x70); }

__device__ __forceinline__ void ldsm4(uint32_t* r, uint32_t addr) {
    asm volatile("ldmatrix.sync.aligned.m8n8.x4.shared.b16 {%0,%1,%2,%3}, [%4];"
                 : "=r"(r[0]), "=r"(r[1]), "=r"(r[2]), "=r"(r[3]) : "r"(addr));
}
__device__ __forceinline__ void mma_f16(float* c, const uint32_t* a, const uint32_t* b) {
    asm volatile(
        "mma.sync.aligned.m16n8k16.row.col.f32.f16.f16.f32 "
        "{%0,%1,%2,%3}, {%4,%5,%6,%7}, {%8,%9}, {%0,%1,%2,%3};"
        : "+f"(c[0]), "+f"(c[1]), "+f"(c[2]), "+f"(c[3])
        : "r"(a[0]), "r"(a[1]), "r"(a[2]), "r"(a[3]), "r"(b[0]), "r"(b[1]));
}
__device__ __forceinline__ void cpasync16(uint32_t d, const void* s) {
    asm volatile("cp.async.cg.shared.global [%0], [%1], 16;" :: "r"(d), "l"(s));
}
__device__ __forceinline__ void cp_commit() { asm volatile("cp.async.commit_group;" ::: "memory"); }
template<int N> __device__ __forceinline__ void cp_wait() {
    asm volatile("cp.async.wait_group %0;" :: "n"(N) : "memory");
}

__device__ __forceinline__ uint32_t pkh(float a, float b) {
    __half2 t = __floats2half2_rn(a, b);
    uint32_t u; memcpy(&u, &t, 4); return u;
}

// load 8 fp32 -> 8 fp16 (16B)
__device__ __forceinline__ uint4 load_h8(const float* p) {
    float4 v0 = *reinterpret_cast<const float4*>(p);
    float4 v1 = *reinterpret_cast<const float4*>(p + 4);
    uint4 o;
    o.x = pkh(v0.x, v0.y); o.y = pkh(v0.z, v0.w);
    o.z = pkh(v1.x, v1.y); o.w = pkh(v1.z, v1.w);
    return o;
}

__device__ __forceinline__ void split1h(float v, __half* h, __half* l) {
    __half hh = __float2half_rn(v);
    *h = hh;
    *l = __float2half_rn(v - __half2float(hh));
}

// ---------------- prep kernels ----------------
__global__ void prep_lam_kernel(const float* __restrict__ nu_log,
                                const float* __restrict__ th_log,
                                const float* __restrict__ rlog) {
    int i = blockIdx.x * blockDim.x + threadIdx.x;
    if (i < NL*DS) {
        float nu = expf(nu_log[i]);
        float r  = expf(-nu);
        float th = expf(th_log[i]);
        g_lre[i] = r * cosf(th);
        g_lim[i] = r * sinf(th);
    }
    if (i < NL) g_sres[i] = 1.0f / (1.0f + expf(-rlog[i]));
}

#define PW_WB   (NL*DM*DM)
#define PW_ENC  (PW_WB + DM*DIN)
#define PW_WC   (PW_ENC + NL*DM*DM)
#define PW_DEC  (PW_WC + 128*DM)
#define PW_WG   (PW_DEC + NL*2*DM*DM)

__global__ void prep_weights_kernel(const float* __restrict__ Bre, const float* __restrict__ Bim,
                                    const float* __restrict__ enc_w,
                                    const float* __restrict__ Cre, const float* __restrict__ Cim,
                                    const float* __restrict__ dec_w,
                                    const float* __restrict__ W1, const float* __restrict__ W2,
                                    const float* __restrict__ nu_log) {
    int idx = blockIdx.x * blockDim.x + threadIdx.x;
    if (idx < PW_WB) {
        int l = idx / (DM*DM), rem = idx - l*(DM*DM);
        int n = rem / DM, k = rem - n*DM;
        int ns = (n < DS) ? n : n - DS;
        float r = expf(-expf(nu_log[l*DS + ns]));
        float gam = sqrtf(fmaxf(1.0f - r*r, 0.0f));
        float v = gam * ((n < DS) ? Bre[((size_t)l*DS + n)*DM + k]
                                  : Bim[((size_t)l*DS + (n-DS))*DM + k]);
        g_Wb[idx] = __float2half_rn(v);
    } else if (idx < PW_ENC) {
        int e = idx - PW_WB;
        split1h(enc_w[e], &g_enchi[e], &g_enclo[e]);
    } else if (idx < PW_WC) {
        int e = idx - PW_ENC;
        int l = e / (DM*DM), rem = e - l*(DM*DM);
        int d = rem / DM, k = rem - d*DM;
        float v;
        if (k < DS) v =  Cre[((size_t)l*DM + d)*DS + k];
        else        v = -Cim[((size_t)l*DM + d)*DS + (k-DS)];
        g_Wc[e] = __float2half_rn(v);
    } else if (idx < PW_DEC) {
        int e = idx - PW_WC;
        int row = e / DM;
        float v = (row < DOUT) ? dec_w[e] : 0.0f;
        split1h(v, &g_dechi[e], &g_declo[e]);
    } else if (idx < PW_WG) {
        int e = idx - PW_DEC;
        int l = e / (2*DM*DM), rem = e - l*(2*DM*DM);
        int n = rem / DM, k = rem - n*DM;
        int o = n >> 1;
        float v = (n & 1) ? W2[((size_t)l*DM + o)*DM + k]
                          : W1[((size_t)l*DM + o)*DM + k];
        g_Wg[e] = __float2half_rn(v);
    }
}

// ---------------- HMMA GEMM: BK=64, multi-stage cp.async pipeline ----------------
// A: fp32 (inline cvt, encoder only) or fp16 (cp.async, AH).
// W: fp16 single (cp.async) or hi+lo (WLO, cp.async, lo at +16KB).
// Stage: [A 16KB][Whi 16KB][Wlo 16KB if WLO]. NSTG = WLO ? 2 : 3 (96KB both).
// EPI: 0 plain, 1 += Dvec[n]*Xres[m,n], 2 GLU: Xout[m,n/2] += s*even*sigmoid(odd)
// OUTH: C fp16. OUTB: also write fp16 shadow (Chalf).

// A fp16 fill (64B half-row per thread, 4 cp.async)
__device__ __forceinline__ void fill_a16(const __half* __restrict__ Ah,
                                         int bm, int K, int k0, uint32_t adst, int tid) {
    const int row  = tid >> 1;
    const int part = tid & 1;
    const char* src = (const char*)(Ah + (size_t)(bm + row)*K + k0 + part*32);
    const uint32_t b0 = (uint32_t)(row*128 + part*64);
#pragma unroll
    for (int q = 0; q < 4; q++)
        cpasync16(adst + sw128(b0 + q*16), src + q*16);
}

// W single-fp16 fill (64B half-row per thread)
__device__ __forceinline__ void fill_w1(const __half* __restrict__ Whi,
                                        int bn, int K, int k0, uint32_t wdst, int tid) {
    const int row  = tid >> 1;
    const int part = tid & 1;
    const char* src = (const char*)(Whi + (size_t)(bn + row)*K + k0 + part*32);
    const uint32_t b0 = (uint32_t)(row*128 + part*64);
#pragma unroll
    for (int q = 0; q < 4; q++)
        cpasync16(wdst + sw128(b0 + q*16), src + q*16);
}

// W hi+lo fill (tid<128: hi rows; tid>=128: lo rows; 128B per thread)
__device__ __forceinline__ void fill_w2(const __half* __restrict__ Whi,
                                        const __half* __restrict__ Wlo,
                                        int bn, int K, int k0, uint32_t wdst, int tid) {
    const int row = tid & 127;
    const int sel = tid >> 7;
    const char* src = (const char*)((sel ? Wlo : Whi) + (size_t)(bn + row)*K + k0);
    const uint32_t base = (uint32_t)(sel*16384) ;
    const uint32_t b0 = (uint32_t)(row*128);
#pragma unroll
    for (int q = 0; q < 8; q++)
        cpasync16(wdst + base + sw128(b0 + q*16), src + q*16);
}

// fp32 A fill (encoder; 32 floats -> 64B per thread, direct cvt+store)
__device__ __forceinline__ void fill_a32(const float* __restrict__ Af, char* sm,
                                         int bm, int K, int k0, int tid) {
    const int row  = tid >> 1;
    const int half = tid & 1;
    const float* src = Af + (size_t)(bm + row)*K + k0 + half*32;
#pragma unroll
    for (int q = 0; q < 4; q++) {
        uint4 v = load_h8(src + q*8);
        *reinterpret_cast<uint4*>(sm + sw128((uint32_t)(row*128 + half*64 + q*16))) = v;
    }
}

template<int EPI, bool WGUARD, bool WLO, bool AH, bool OUTH, bool OUTB>
__global__ __launch_bounds__(256, 2)
void hmma_gemm(const void* __restrict__ Ain,
               const __half* __restrict__ Whi, const __half* __restrict__ Wlo,
               void* __restrict__ Cout, __half* __restrict__ Chalf, int K, int Ntot,
               const float* __restrict__ Dvec, const float* __restrict__ Xres,
               const float* __restrict__ sres_p, float* __restrict__ Xout) {
    constexpr int WBYTES = WLO ? 32768 : 16384;
    constexpr int STAGE  = 16384 + WBYTES;
    constexpr int NSTG   = WLO ? 2 : 3;

    extern __shared__ char smem[];
    const uint32_t s0 = smem_u32(smem);
    const int tid  = threadIdx.x;
    const int wid  = tid >> 5;
    const int lane = tid & 31;
    const int wm   = wid & 1;
    const int wn   = wid >> 1;
    const int bm   = blockIdx.y * 128;
    const int bn   = blockIdx.x * 128;

    const float*  Af = (const float*)Ain;
    const __half* Ah = (const __half*)Ain;

    float acc[4][4][4];
#pragma unroll
    for (int i = 0; i < 4; i++)
#pragma unroll
        for (int j = 0; j < 4; j++)
#pragma unroll
            for (int q = 0; q < 4; q++) acc[i][j][q] = 0.0f;

    const int NK = K >> 6;   // chunks of 64

    // prologue: fill chunks 0..NSTG-2
#pragma unroll
    for (int p = 0; p < NSTG-1; ++p) {
        if (p < NK) {
            const uint32_t sb = s0 + p*STAGE;
            if (AH) fill_a16(Ah, bm, K, p*64, sb, tid);
            else    fill_a32(Af, smem + p*STAGE, bm, K, p*64, tid);
            if (WLO) fill_w2(Whi, Wlo, bn, K, p*64, sb + 16384, tid);
            else     fill_w1(Whi,      bn, K, p*64, sb + 16384, tid);
            cp_commit();
        }
    }

    const int a_row = wm*64 + (lane & 7) + ((lane >> 3) & 1)*8;
    const int a_kb  = (lane >> 4) << 4;
    const int b_sub = lane >> 3;
    const int b_row = wn*32 + (lane & 7) + (b_sub >> 1)*8;
    const int b_kb  = (b_sub & 1) << 4;

    for (int t = 0; t < NK; ++t) {
        // wait until chunk t's group has landed (leave later fills in flight)
        if (t + NSTG <= NK)      cp_wait<NSTG-1>();
        else if (t + 2 <= NK)    cp_wait<1>();
        else                     cp_wait<0>();
        __syncthreads();     // all warps done reading the stage being refilled

        const int fc = t + NSTG - 1;
        if (fc < NK) {
            const int   fs = fc % NSTG;
            const uint32_t sb = s0 + fs*STAGE;
            if (AH) fill_a16(Ah, bm, K, fc*64, sb, tid);
            else    fill_a32(Af, smem + fs*STAGE, bm, K, fc*64, tid);
            if (WLO) fill_w2(Whi, Wlo, bn, K, fc*64, sb + 16384, tid);
            else     fill_w1(Whi,      bn, K, fc*64, sb + 16384, tid);
            cp_commit();
        }

        const uint32_t As = s0 + (t % NSTG)*STAGE;
        const uint32_t Ws = As + 16384;
#pragma unroll
        for (int s = 0; s < 4; ++s) {   // 4 x K=16 within the 64-chunk
            uint32_t bh[4][2], bl[4][2];
#pragma unroll
            for (int jj = 0; jj < 2; jj++) {
                uint32_t base = (uint32_t)((b_row + 16*jj)*128 + s*32 + b_kb);
                uint32_t r[4];
                ldsm4(r, Ws + sw128(base));
                bh[2*jj][0] = r[0]; bh[2*jj][1] = r[1];
                bh[2*jj+1][0] = r[2]; bh[2*jj+1][1] = r[3];
                if (WLO) {
                    ldsm4(r, Ws + 16384 + sw128(base));
                    bl[2*jj][0] = r[0]; bl[2*jj][1] = r[1];
                    bl[2*jj+1][0] = r[2]; bl[2*jj+1][1] = r[3];
                }
            }
#pragma unroll
            for (int i = 0; i < 4; i++) {
                uint32_t ah[4];
                uint32_t base = (uint32_t)((a_row + 16*i)*128 + s*32 + a_kb);
                ldsm4(ah, As + sw128(base));
#pragma unroll
                for (int j = 0; j < 4; j++) {
                    mma_f16(acc[i][j], ah, bh[j]);
                    if (WLO) mma_f16(acc[i][j], ah, bl[j]);
                }
            }
        }
    }

    // epilogue
    const int gid = lane >> 2;
    const int tg  = lane & 3;
#pragma unroll
    for (int i = 0; i < 4; i++) {
        const int r0 = bm + wm*64 + i*16 + gid;
#pragma unroll
        for (int j = 0; j < 4; j++) {
            const int col = bn + wn*32 + j*8 + tg*2;
            if (EPI == 2) {
                const float s = *sres_p;
                const int oc = col >> 1;
                size_t i0 = (size_t)r0 * DM + oc;
                size_t i1 = (size_t)(r0+8) * DM + oc;
                float x0 = fmaf(s * acc[i][j][0], 1.0f/(1.0f + expf(-acc[i][j][1])), Xout[i0]);
                float x1 = fmaf(s * acc[i][j][2], 1.0f/(1.0f + expf(-acc[i][j][3])), Xout[i1]);
                Xout[i0] = x0; Xout[i1] = x1;
                if (OUTB) {
                    Chalf[i0] = __float2half_rn(x0);
                    Chalf[i1] = __float2half_rn(x1);
                }
            } else {
                if (WGUARD && col >= Ntot) continue;
                float2 v0 = make_float2(acc[i][j][0], acc[i][j][1]);
                float2 v1 = make_float2(acc[i][j][2], acc[i][j][3]);
                if (EPI == 1) {
                    const float2 d  = *reinterpret_cast<const float2*>(Dvec + col);
                    const float2 x0 = *reinterpret_cast<const float2*>(Xres + (size_t)r0*Ntot + col);
                    const float2 x1 = *reinterpret_cast<const float2*>(Xres + (size_t)(r0+8)*Ntot + col);
                    v0.x = fmaf(d.x, x0.x, v0.x); v0.y = fmaf(d.y, x0.y, v0.y);
                    v1.x = fmaf(d.x, x1.x, v1.x); v1.y = fmaf(d.y, x1.y, v1.y);
                }
                size_t i0 = (size_t)r0*Ntot + col;
                size_t i1 = (size_t)(r0+8)*Ntot + col;
                if (OUTH) {
                    *(__half2*)((__half*)Cout + i0) = __floats2half2_rn(v0.x, v0.y);
                    *(__half2*)((__half*)Cout + i1) = __floats2half2_rn(v1.x, v1.y);
                } else {
                    *reinterpret_cast<float2*>((float*)Cout + i0) = v0;
                    *reinterpret_cast<float2*>((float*)Cout + i1) = v1;
                    if (OUTB) {
                        *(__half2*)(Chalf + i0) = __floats2half2_rn(v0.x, v0.y);
                        *(__half2*)(Chalf + i1) = __floats2half2_rn(v1.x, v1.y);
                    }
                }
            }
        }
    }
}

// ---------------- two-phase chunked LRU scan (fp16 I/O, fp32 internal) --------
__global__ void scan_ends_kernel(const __half* __restrict__ Bu,
                                 const float* __restrict__ lre_g,
                                 const float* __restrict__ lim_g) {
    int n = threadIdx.x;
    int b = blockIdx.x;
    int c = blockIdx.y;
    float lre = lre_g[n], lim = lim_g[n];
    size_t base = ((size_t)b * LSEQ + (size_t)c * CHLEN) * DM + n;
    float hre = 0.0f, him = 0.0f;
#pragma unroll 4
    for (int t = 0; t < CHLEN; ++t) {
        size_t off = base + (size_t)t * DM;
        float bre = __half2float(Bu[off]);
        float bim = __half2float(Bu[off + DS]);
        float nre = fmaf(lre, hre, fmaf(-lim, him, bre));
        float nim = fmaf(lim, hre, fmaf( lre, him, bim));
        hre = nre; him = nim;
    }
    int ci = b * NCH + c;
    g_cend[(size_t)ci*2*DS + n]      = hre;
    g_cend[(size_t)ci*2*DS + DS + n] = him;
}

__global__ void scan_apply_kernel(const __half* __restrict__ Bu, __half* __restrict__ H,
                                  const float* __restrict__ lre_g,
                                  const float* __restrict__ lim_g) {
    int n = threadIdx.x;
    int b = blockIdx.x;
    int c = blockIdx.y;
    float lre = lre_g[n], lim = lim_g[n];
    float Pre = lre, Pim = lim;
#pragma unroll
    for (int i = 0; i < 7; i++) {
        float t = Pre*Pre - Pim*Pim;
        Pim = 2.0f*Pre*Pim;
        Pre = t;
    }
    float hre = 0.0f, him = 0.0f;
    for (int j = 0; j < c; ++j) {
        size_t cj = (size_t)(b * NCH + j) * 2 * DS;
        float ere = g_cend[cj + n];
        float eim = g_cend[cj + DS + n];
        float nre = fmaf(Pre, hre, fmaf(-Pim, him, ere));
        float nim = fmaf(Pim, hre, fmaf( Pre, him, eim));
        hre = nre; him = nim;
    }
    size_t base = ((size_t)b * LSEQ + (size_t)c * CHLEN) * DM + n;
#pragma unroll 4
    for (int t = 0; t < CHLEN; ++t) {
        size_t off = base + (size_t)t * DM;
        float bre = __half2float(Bu[off]);
        float bim = __half2float(Bu[off + DS]);
        float nre = fmaf(lre, hre, fmaf(-lim, him, bre));
        float nim = fmaf(lim, hre, fmaf( lre, him, bim));
        hre = nre; him = nim;
        H[off]      = __float2half_rn(hre);
        H[off + DS] = __float2half_rn(him);
    }
}

// ---------------- host launch ----------------
extern "C" void kernel_launch(void* const* d_in, const int* in_sizes, int n_in,
                              void* d_out, int out_size) {
    const float* u      = (const float*)d_in[0];
    const float* enc_w  = (const float*)d_in[1];
    const float* dec_w  = (const float*)d_in[2];
    const float* nu_log = (const float*)d_in[3];
    const float* th_log = (const float*)d_in[4];
    const float* Bre    = (const float*)d_in[5];
    const float* Bim    = (const float*)d_in[6];
    const float* Cre    = (const float*)d_in[7];
    const float* Cim    = (const float*)d_in[8];
    const float* Dv     = (const float*)d_in[9];
    const float* W1     = (const float*)d_in[10];
    const float* W2     = (const float*)d_in[11];
    const float* rlog   = (const float*)d_in[12];
    float* out = (float*)d_out;

    float *px, *plre, *plim, *psres;
    __half *pxh, *pbuh, *phh, *pzh, *pWb, *pWc, *pWg;
    __half *penchi, *penclo, *pdechi, *pdeclo;
    cudaGetSymbolAddress((void**)&px,   g_x);
    cudaGetSymbolAddress((void**)&pxh,  g_xh);
    cudaGetSymbolAddress((void**)&pbuh, g_buh);
    cudaGetSymbolAddress((void**)&phh,  g_hh);
    cudaGetSymbolAddress((void**)&pzh,  g_zh);
    cudaGetSymbolAddress((void**)&pWb,  g_Wb);
    cudaGetSymbolAddress((void**)&pWc,  g_Wc);
    cudaGetSymbolAddress((void**)&pWg,  g_Wg);
    cudaGetSymbolAddress((void**)&penchi, g_enchi); cudaGetSymbolAddress((void**)&penclo, g_enclo);
    cudaGetSymbolAddress((void**)&pdechi, g_dechi); cudaGetSymbolAddress((void**)&pdeclo, g_declo);
    cudaGetSymbolAddress((void**)&plre,  g_lre);
    cudaGetSymbolAddress((void**)&plim,  g_lim);
    cudaGetSymbolAddress((void**)&psres, g_sres);

    const int SMEM = 98304;   // 96 KB per CTA -> 2 CTAs/SM (192KB <= 228KB)
    cudaFuncSetAttribute(hmma_gemm<0,false,true ,false,false,true >, cudaFuncAttributeMaxDynamicSharedMemorySize, SMEM);
    cudaFuncSetAttribute(hmma_gemm<0,false,false,true ,true ,false>, cudaFuncAttributeMaxDynamicSharedMemorySize, SMEM);
    cudaFuncSetAttribute(hmma_gemm<1,false,false,true ,true ,false>, cudaFuncAttributeMaxDynamicSharedMemorySize, SMEM);
    cudaFuncSetAttribute(hmma_gemm<2,false,false,true ,false,true >, cudaFuncAttributeMaxDynamicSharedMemorySize, SMEM);
    cudaFuncSetAttribute(hmma_gemm<0,true ,true ,true ,false,false>, cudaFuncAttributeMaxDynamicSharedMemorySize, SMEM);

    // prep (2 launches; prep_weights is the clock-state sentinel)
    prep_lam_kernel    <<<(NL*DS + 255)/256, 256>>>(nu_log, th_log, rlog);
    prep_weights_kernel<<<(PW_WG + 255)/256, 256>>>(Bre, Bim, enc_w, Cre, Cim, dec_w, W1, W2, nu_log);

    // encoder: x = u @ enc_w^T  (fp32 A, hi+lo W, K=64 -> NK=1) -> fp32 x + fp16 xh
    hmma_gemm<0,false,true,false,false,true><<<dim3(DM/128, MTOK/128), 256, SMEM>>>(
        u, penchi, penclo, px, pxh, DIN, DM, nullptr, nullptr, nullptr, nullptr);

    for (int l = 0; l < NL; ++l) {
        const float* lre = plre + l*DS;
        const float* lim = plim + l*DS;
        // Bu = xh @ Wb^T (fp16 A, 3-stage, fp16 out)
        hmma_gemm<0,false,false,true,true,false><<<dim3(DM/128, MTOK/128), 256, SMEM>>>(
            pxh, pWb + (size_t)l*DM*DM, nullptr,
            pbuh, nullptr, DM, DM, nullptr, nullptr, nullptr, nullptr);
        // two-phase scan (fp16 I/O, fp32 internal)
        scan_ends_kernel <<<dim3(NB, NCH), DS>>>(pbuh, lre, lim);
        scan_apply_kernel<<<dim3(NB, NCH), DS>>>(pbuh, phh, lre, lim);
        // z = Re(C h) + D*x (fp16 A=h, 3-stage, fp16 z out; D*x from fp32 x)
        hmma_gemm<1,false,false,true,true,false><<<dim3(DM/128, MTOK/128), 256, SMEM>>>(
            phh, pWc + (size_t)l*DM*DM, nullptr,
            pzh, nullptr, DM, DM, Dv + l*DM, px, nullptr, nullptr);
        // GLU GEMM (fp16 A=z, 3-stage): x += s*g1*sigmoid(g2), update x + xh
        hmma_gemm<2,false,false,true,false,true><<<dim3(2*DM/128, MTOK/128), 256, SMEM>>>(
            pzh, pWg + (size_t)l*2*DM*DM, nullptr,
            nullptr, pxh, DM, 2*DM, nullptr, nullptr, psres + l, px);
    }

    // decoder: out = xh @ dec_w^T (fp16 A, hi+lo W, 2-stage, N=64 guarded)
    hmma_gemm<0,true,true,true,false,false><<<dim3(1, MTOK/128), 256, SMEM>>>(
        pxh, pdechi, pdeclo, out, nullptr, DM, DOUT, nullptr, nullptr, nullptr, nullptr);
}